// round 13
// baseline (speedup 1.0000x reference)
#include <cuda_runtime.h>

// ---------------- problem constants ----------------
#define BB     2048
#define WAYS   64
#define SHOT   32
#define LAT    512
#define FLATD  6272
#define EPSBN  1e-5f
#define SLOPE  0.2f

#define OFF_RECON 0
#define OFF_PROTO 1605632
#define OFF_RAD   1638400
#define OFF_LAT   1671168

// ---------------- scratch (device globals; no runtime alloc) ----------------
__device__ float g_h1 [BB*64*196];   // conv1 raw
__device__ float g_h2 [BB*128*49];   // conv2 raw
__device__ float g_lat[BB*LAT];      // latent pre-BN
__device__ float g_xrec[BB*LAT];     // shifted latent
__device__ float g_fc [BB*FLATD];    // fc raw
__device__ float g_d1 [BB*64*196];   // deconv1 raw
__device__ float g_d2 [BB*784];      // deconv2 raw
__device__ float g_gpart[4*BB*LAT];  // split-K partials

__device__ float g_ps[1835008];      // BN partial sums
__device__ float g_pq[1835008];      // BN partial sumsq

__device__ float g_a1[64],  g_b1[64];
__device__ float g_a2[128], g_b2[128];
__device__ float g_aL[LAT], g_bL[LAT];
__device__ float g_aF[FLATD], g_bF[FLATD];
__device__ float g_aD1[64], g_bD1[64];
__device__ float g_aD2[1],  g_bD2[1];

__device__ __forceinline__ float leakyf(float v){ return v >= 0.f ? v : SLOPE*v; }
__device__ __forceinline__ float sigmoidf(float v){ return 1.f/(1.f+__expf(-v)); }

// ---------------- BN finalize, layout A: g_ps[c*S + i] ----------------
__global__ void bn_finalize2(int S, float invN,
                             const float* __restrict__ scale, const float* __restrict__ bias,
                             float* __restrict__ ga, float* __restrict__ gb)
{
    int c = blockIdx.x;
    __shared__ float rs[128], rq[128];
    float s = 0.f, q = 0.f;
    for (int i = threadIdx.x; i < S; i += 128) {
        s += g_ps[(size_t)c*S + i];
        q += g_pq[(size_t)c*S + i];
    }
    rs[threadIdx.x] = s; rq[threadIdx.x] = q;
    __syncthreads();
    for (int st = 64; st > 0; st >>= 1) {
        if (threadIdx.x < st) { rs[threadIdx.x] += rs[threadIdx.x+st]; rq[threadIdx.x] += rq[threadIdx.x+st]; }
        __syncthreads();
    }
    if (threadIdx.x == 0) {
        float m = rs[0] * invN;
        float v = rq[0] * invN - m * m;
        float inv = rsqrtf(v + EPSBN);
        float a = scale[c] * inv;
        ga[c] = a;
        gb[c] = bias[c] - m * a;
    }
}

// ---------------- BN finalize, layout B: g_ps[b*stride + c*P + p] — 512 threads ----------------
__global__ void __launch_bounds__(512) bn_finalize3(int nb, int P, int stride, float invN,
                             const float* __restrict__ scale, const float* __restrict__ bias,
                             float* __restrict__ ga, float* __restrict__ gb)
{
    int c = blockIdx.x;
    __shared__ float rs[512], rq[512];
    float s = 0.f, q = 0.f;
    int n = nb * P;
    for (int i = threadIdx.x; i < n; i += 512) {
        int b = i / P, p = i % P;
        size_t idx = (size_t)b*stride + c*P + p;
        s += g_ps[idx];
        q += g_pq[idx];
    }
    rs[threadIdx.x] = s; rq[threadIdx.x] = q;
    __syncthreads();
    for (int st = 256; st > 0; st >>= 1) {
        if (threadIdx.x < st) { rs[threadIdx.x] += rs[threadIdx.x+st]; rq[threadIdx.x] += rq[threadIdx.x+st]; }
        __syncthreads();
    }
    if (threadIdx.x == 0) {
        float m = rs[0] * invN;
        float v = rq[0] * invN - m * m;
        float inv = rsqrtf(v + EPSBN);
        float a = scale[c] * inv;
        ga[c] = a;
        gb[c] = bias[c] - m * a;
    }
}

// ---------------- conv1: [B,1,28,28] -> [B,64,14,14], register-stationary + free stats ----------------
__global__ void __launch_bounds__(256) conv1_kernel(const float* __restrict__ x,
                             const float* __restrict__ w, const float* __restrict__ bias)
{
    int b = blockIdx.x;
    __shared__ float sx[784];
    __shared__ float sw[1024];
    int tid = threadIdx.x;
    for (int i = tid; i < 784;  i += 256) sx[i] = x[b*784 + i];
    for (int i = tid; i < 1024; i += 256) sw[i] = w[i];
    __syncthreads();

    int c = tid >> 2, qd = tid & 3;
    float bb = bias[c];
    const float* wc = &sw[c*16];
    float* dst = &g_h1[(size_t)(b*64 + c)*196];
    float s = 0.f, q = 0.f;
    #pragma unroll 7
    for (int t = 0; t < 49; t++) {
        int pix = qd*49 + t;
        int oy = pix / 14, ox = pix % 14;
        float acc = bb;
        #pragma unroll
        for (int ky = 0; ky < 4; ky++) {
            int iy = 2*oy + ky - 1;
            if ((unsigned)iy < 28u) {
                #pragma unroll
                for (int kx = 0; kx < 4; kx++) {
                    int ix = 2*ox + kx - 1;
                    if ((unsigned)ix < 28u)
                        acc += sx[iy*28+ix] * wc[ky*4+kx];
                }
            }
        }
        dst[pix] = acc;
        s += acc; q += acc*acc;
    }
    g_ps[(size_t)b*256 + tid] = s;   // layout B: stride=256, P=4
    g_pq[(size_t)b*256 + tid] = q;
}

// ---------------- conv2: [B,64,14,14] -> [B,128,7,7], bn1+leaky fused, free stats ----------------
// 112 threads: (channel-group-of-8, oy). Each 14-wide smem row read feeds 224 FMAs.
// Weights consumed in two 4-channel passes to cap live registers. float4 staging.
__global__ void __launch_bounds__(112) conv2_kernel(const float* __restrict__ w,
                                                    const float* __restrict__ bias)
{
    int b = blockIdx.x;
    __shared__ __align__(16) float sin2[32*196];   // 25088 B
    int tid = threadIdx.x;
    int cg = tid / 7, oy = tid % 7;
    int co = 8*cg;
    float acc[8][7];
    #pragma unroll
    for (int u = 0; u < 8; u++) {
        float bb = bias[co+u];
        #pragma unroll
        for (int j = 0; j < 7; j++) acc[u][j] = bb;
    }

    for (int cc = 0; cc < 64; cc += 32) {
        __syncthreads();   // previous chunk fully consumed
        const float4* src4 = reinterpret_cast<const float4*>(g_h1 + ((size_t)b*64 + cc)*196);
        float4* dst4 = reinterpret_cast<float4*>(sin2);
        for (int i = tid; i < 1568; i += 112) {      // 32*196/4; 49 float4 per channel row
            int c = cc + i/49;
            float a = g_a1[c], bo = g_b1[c];
            float4 v = src4[i];
            v.x = leakyf(a*v.x + bo); v.y = leakyf(a*v.y + bo);
            v.z = leakyf(a*v.z + bo); v.w = leakyf(a*v.w + bo);
            dst4[i] = v;
        }
        __syncthreads();
        for (int ci = 0; ci < 32; ci++) {
            const float* inc = &sin2[ci*196];
            int cig = cc + ci;
            #pragma unroll
            for (int ky = 0; ky < 4; ky++) {
                int iy = 2*oy + ky - 1;
                if ((unsigned)iy >= 14u) continue;
                float rE[16];
                rE[0] = 0.f; rE[15] = 0.f;
                #pragma unroll
                for (int t = 0; t < 14; t++) rE[t+1] = inc[iy*14 + t];
                #pragma unroll
                for (int up = 0; up < 2; up++) {
                    float4 wv[4];
                    #pragma unroll
                    for (int v = 0; v < 4; v++)
                        wv[v] = *reinterpret_cast<const float4*>(
                            &w[(size_t)((co + up*4 + v)*64 + cig)*16 + ky*4]);
                    #pragma unroll
                    for (int ox = 0; ox < 7; ox++) {
                        int p = 2*ox;
                        float e0 = rE[p], e1 = rE[p+1], e2 = rE[p+2], e3 = rE[p+3];
                        #pragma unroll
                        for (int v = 0; v < 4; v++)
                            acc[up*4+v][ox] += e0*wv[v].x + e1*wv[v].y + e2*wv[v].z + e3*wv[v].w;
                    }
                }
            }
        }
    }
    #pragma unroll
    for (int u = 0; u < 8; u++) {
        float s = 0.f, q = 0.f;
        #pragma unroll
        for (int ox = 0; ox < 7; ox++) {
            float v = acc[u][ox];
            g_h2[(size_t)(b*128 + co+u)*49 + oy*7 + ox] = v;
            s += v; q += v*v;
        }
        g_ps[(size_t)b*896 + (co+u)*7 + oy] = s;   // layout B: stride=896, P=7
        g_pq[(size_t)b*896 + (co+u)*7 + oy] = q;
    }
}

// ---------------- SGEMM NT: C[M,N] = act(A)[M,K] * W[N,K]^T (+bias) ----------------
// MODE 1: latent GEMM, A gets bn2-affine + leaky (c=k/49), split-K partial output.
// MODE 0: fc GEMM, bias added, fused per-column BN partial stats (layout A, S=16).
template<int MODE>
__global__ void __launch_bounds__(256) sgemm_nt(
    const float* __restrict__ A, const float* __restrict__ W,
    const float* __restrict__ bias, float* __restrict__ out,
    int M, int N, int K, int Ktile,
    const float* __restrict__ ca, const float* __restrict__ cb)
{
    __shared__ float As[16][128];
    __shared__ float Bs[16][128];
    const int tid = threadIdx.x;
    const int bm = blockIdx.y * 128;
    const int bn = blockIdx.x * 128;
    const int lr = tid >> 2;
    const int lc = (tid & 3) << 2;
    const int tm = (tid >> 4) << 3;
    const int tn = (tid & 15) << 3;
    float acc[8][8];
    #pragma unroll
    for (int i = 0; i < 8; i++)
        #pragma unroll
        for (int j = 0; j < 8; j++) acc[i][j] = 0.f;

    const int k0beg = blockIdx.z * Ktile;
    for (int k0 = k0beg; k0 < k0beg + Ktile; k0 += 16) {
        #pragma unroll
        for (int h = 0; h < 2; h++) {
            int row = bm + lr + (h << 6);
            float4 v = *reinterpret_cast<const float4*>(A + (size_t)row*K + k0 + lc);
            if (MODE == 1) {
                int kb = k0 + lc;
                int c0 = (kb  )/49, c1 = (kb+1)/49, c2 = (kb+2)/49, c3 = (kb+3)/49;
                v.x = leakyf(ca[c0]*v.x + cb[c0]);
                v.y = leakyf(ca[c1]*v.y + cb[c1]);
                v.z = leakyf(ca[c2]*v.z + cb[c2]);
                v.w = leakyf(ca[c3]*v.w + cb[c3]);
            }
            As[lc+0][lr+(h<<6)] = v.x; As[lc+1][lr+(h<<6)] = v.y;
            As[lc+2][lr+(h<<6)] = v.z; As[lc+3][lr+(h<<6)] = v.w;

            int wrow = bn + lr + (h << 6);
            float4 wv = *reinterpret_cast<const float4*>(W + (size_t)wrow*K + k0 + lc);
            Bs[lc+0][lr+(h<<6)] = wv.x; Bs[lc+1][lr+(h<<6)] = wv.y;
            Bs[lc+2][lr+(h<<6)] = wv.z; Bs[lc+3][lr+(h<<6)] = wv.w;
        }
        __syncthreads();
        #pragma unroll
        for (int kk = 0; kk < 16; kk++) {
            float a[8], bb[8];
            #pragma unroll
            for (int i = 0; i < 8; i++) a[i]  = As[kk][tm+i];
            #pragma unroll
            for (int j = 0; j < 8; j++) bb[j] = Bs[kk][tn+j];
            #pragma unroll
            for (int i = 0; i < 8; i++)
                #pragma unroll
                for (int j = 0; j < 8; j++) acc[i][j] += a[i]*bb[j];
        }
        __syncthreads();
    }

    if (MODE == 0) {
        float cs[8], cq[8];
        #pragma unroll
        for (int j = 0; j < 8; j++) { cs[j] = 0.f; cq[j] = 0.f; }
        #pragma unroll
        for (int i = 0; i < 8; i++) {
            float* o = out + (size_t)(bm+tm+i)*N + bn;
            #pragma unroll
            for (int j = 0; j < 8; j++) {
                float v = acc[i][j] + bias[bn+tn+j];
                o[tn+j] = v;
                cs[j] += v; cq[j] += v*v;
            }
        }
        // reduce per-column partials through As/Bs (free after last loop sync)
        int g = tid >> 4;
        #pragma unroll
        for (int j = 0; j < 8; j++) { As[g][tn+j] = cs[j]; Bs[g][tn+j] = cq[j]; }
        __syncthreads();
        if (tid < 128) {
            float s = 0.f, q = 0.f;
            #pragma unroll
            for (int g2 = 0; g2 < 16; g2++) { s += As[g2][tid]; q += Bs[g2][tid]; }
            g_ps[(size_t)(bn+tid)*16 + blockIdx.y] = s;
            g_pq[(size_t)(bn+tid)*16 + blockIdx.y] = q;
        }
    } else {
        float* P = out + (size_t)blockIdx.z * M * N;
        #pragma unroll
        for (int i = 0; i < 8; i++) {
            float* o = P + (size_t)(bm+tm+i)*N + bn;
            #pragma unroll
            for (int j = 0; j < 8; j++) o[tn+j] = acc[i][j];
        }
    }
}

// ---------------- combine split-K partials + bias, fused latent BN stats (layout A, S=32) ----------------
__global__ void __launch_bounds__(512) combine_lat_stats(const float* __restrict__ bias)
{
    int c = threadIdx.x;
    int s = blockIdx.x;
    float bc = bias[c];
    float sum = 0.f, sq = 0.f;
    for (int r = s*64; r < s*64 + 64; r++) {
        size_t idx = (size_t)r*LAT + c;
        float v = g_gpart[idx] + g_gpart[(size_t)BB*LAT + idx]
                + g_gpart[2*(size_t)BB*LAT + idx] + g_gpart[3*(size_t)BB*LAT + idx] + bc;
        g_lat[idx] = v;
        sum += v; sq += v*v;
    }
    g_ps[(size_t)c*32 + s] = sum;
    g_pq[(size_t)c*32 + s] = sq;
}

// ---------------- latent activation / proto / attention ----------------
__global__ void latent_act(float* __restrict__ xlat)
{
    int idx = blockIdx.x * blockDim.x + threadIdx.x;
    if (idx >= BB*LAT) return;
    int c = idx & (LAT-1);
    xlat[idx] = sigmoidf(g_aL[c]*g_lat[idx] + g_bL[c]);
}

__global__ void proto_kernel(const float* __restrict__ xlat, float* __restrict__ proto)
{
    int w = blockIdx.x, l = threadIdx.x;
    float s = 0.f;
    #pragma unroll
    for (int j = 0; j < SHOT; j++) s += xlat[(size_t)(w*SHOT + j)*LAT + l];
    proto[w*LAT + l] = s * (1.f/SHOT);
}

__global__ void attn_radius_kernel(const float* __restrict__ proto, float* __restrict__ radius)
{
    int i = blockIdx.x;
    int tid = threadIdx.x;   // 64
    __shared__ float spi[LAT];
    __shared__ float att[WAYS];
    for (int l = tid; l < LAT; l += 64) spi[l] = proto[i*LAT + l];
    __syncthreads();
    float dot = 0.f;
    const float* pj = proto + tid*LAT;
    for (int l = 0; l < LAT; l++) dot += spi[l] * pj[l];
    att[tid] = dot;
    __syncthreads();
    float mx = -1e30f;
    for (int j = 0; j < WAYS; j++) mx = fmaxf(mx, att[j]);
    float ex = __expf(att[tid] - mx);
    __syncthreads();
    att[tid] = ex;
    __syncthreads();
    float sum = 0.f;
    for (int j = 0; j < WAYS; j++) sum += att[j];
    float inv = 1.f / sum;
    for (int r = 0; r < 8; r++) {
        int l = tid + (r << 6);
        float accv = 0.f;
        for (int j = 0; j < WAYS; j++) accv += att[j] * proto[j*LAT + l];
        radius[i*LAT + l] = spi[l] - accv * inv;
    }
}

__global__ void recon_latent(const float* __restrict__ xlat, const float* __restrict__ radius,
                             const float* __restrict__ gamma)
{
    int idx = blockIdx.x * blockDim.x + threadIdx.x;
    if (idx >= BB*LAT) return;
    int c = idx & (LAT-1);
    int m = idx >> 9;
    int w = m >> 5;
    g_xrec[idx] = xlat[idx] + radius[(w << 9) + c] * gamma[0];
}

// ---------------- deconv1: [B,128,7,7] -> [B,64,14,14], bnf fused, free stats ----------------
__global__ void __launch_bounds__(224) deconv1_kernel(const float* __restrict__ w,
                                                      const float* __restrict__ bias)
{
    int b = blockIdx.x;
    __shared__ float sin1[128*49];   // 25088 B
    const float* src = g_fc + (size_t)b * FLATD;
    int tid = threadIdx.x;
    for (int i = tid; i < FLATD; i += 224)
        sin1[i] = g_aF[i] * src[i] + g_bF[i];
    __syncthreads();
    int cg = tid / 14, oy = tid % 14;
    int co = 4*cg;
    float acc[4][14];
    #pragma unroll
    for (int u = 0; u < 4; u++) {
        float bb = bias[co+u];
        #pragma unroll
        for (int j = 0; j < 14; j++) acc[u][j] = bb;
    }
    int kyp = oy & 1;
    for (int ci = 0; ci < 128; ci++) {
        const float* inc = &sin1[ci*49];
        #pragma unroll
        for (int kyi = 0; kyi < 2; kyi++) {
            int ky = kyp + 2*kyi;
            int iy = (oy + ky - 2) >> 1;
            if ((unsigned)iy >= 7u) continue;
            float r[7];
            #pragma unroll
            for (int t = 0; t < 7; t++) r[t] = inc[iy*7 + t];
            float wr[4][4];
            #pragma unroll
            for (int u = 0; u < 4; u++) {
                float4 q = *reinterpret_cast<const float4*>(&w[(size_t)(ci*64 + co+u)*16 + (3-ky)*4]);
                wr[u][0] = q.w; wr[u][1] = q.z; wr[u][2] = q.y; wr[u][3] = q.x;
            }
            #pragma unroll
            for (int ox = 0; ox < 14; ox++) {
                int kxp = ox & 1;
                #pragma unroll
                for (int kxi = 0; kxi < 2; kxi++) {
                    int kx = kxp + 2*kxi;
                    int ix = (ox + kx - 2) >> 1;
                    if ((unsigned)ix < 7u) {
                        float rv = r[ix];
                        #pragma unroll
                        for (int u = 0; u < 4; u++)
                            acc[u][ox] += rv * wr[u][kx];
                    }
                }
            }
        }
    }
    #pragma unroll
    for (int u = 0; u < 4; u++) {
        float s = 0.f, q = 0.f;
        #pragma unroll
        for (int ox = 0; ox < 14; ox++) {
            float v = acc[u][ox];
            g_d1[(size_t)(b*64 + co+u)*196 + oy*14 + ox] = v;
            s += v; q += v*v;
        }
        g_ps[(size_t)b*896 + (co+u)*14 + oy] = s;   // layout B: stride=896, P=14
        g_pq[(size_t)b*896 + (co+u)*14 + oy] = q;
    }
}

// ---------------- deconv2: [B,64,14,14] -> [B,1,28,28], bnd1+leaky fused, fused stats ----------------
__global__ void __launch_bounds__(784) deconv2_kernel(const float* __restrict__ w,
                                                      const float* __restrict__ bias)
{
    int b = blockIdx.x;
    __shared__ float sin3[32*196];   // 25088 B
    __shared__ float swt[1024];
    __shared__ float rs[784], rq[784];
    int tid = threadIdx.x;
    for (int i = tid; i < 1024; i += 784) swt[i] = w[i];

    int oy = tid / 28, ox = tid % 28;
    int kyp = oy & 1, kxp = ox & 1;
    int iy0 = (oy + kyp - 2) >> 1;
    int iy1 = (oy + kyp) >> 1;
    int ix0 = (ox + kxp - 2) >> 1;
    int ix1 = (ox + kxp) >> 1;
    bool vy0 = (unsigned)iy0 < 14u, vy1 = (unsigned)iy1 < 14u;
    bool vx0 = (unsigned)ix0 < 14u, vx1 = (unsigned)ix1 < 14u;
    int o00 = (3-kyp)*4 + (3-kxp);
    int o01 = (3-kyp)*4 + (1-kxp);
    int o10 = (1-kyp)*4 + (3-kxp);
    int o11 = (1-kyp)*4 + (1-kxp);
    float acc = bias[0];

    for (int cc = 0; cc < 64; cc += 32) {
        __syncthreads();
        const float* src = g_d1 + ((size_t)b*64 + cc)*196;
        for (int i = tid; i < 32*196; i += 784) {
            int c = cc + i/196;
            sin3[i] = leakyf(g_aD1[c]*src[i] + g_bD1[c]);
        }
        __syncthreads();
        for (int ci = 0; ci < 32; ci++) {
            const float* sc = &sin3[ci*196];
            const float* wb = &swt[(cc+ci)*16];
            if (vy0 && vx0) acc += sc[iy0*14+ix0] * wb[o00];
            if (vy0 && vx1) acc += sc[iy0*14+ix1] * wb[o01];
            if (vy1 && vx0) acc += sc[iy1*14+ix0] * wb[o10];
            if (vy1 && vx1) acc += sc[iy1*14+ix1] * wb[o11];
        }
    }
    g_d2[(size_t)b*784 + tid] = acc;

    // fused single-channel stats: block reduction of 784 values (layout A, c=0, S=2048)
    rs[tid] = acc; rq[tid] = acc*acc;
    __syncthreads();
    if (tid < 272) { rs[tid] += rs[tid+512]; rq[tid] += rq[tid+512]; }
    __syncthreads();
    for (int st = 256; st > 0; st >>= 1) {
        if (tid < st) { rs[tid] += rs[tid+st]; rq[tid] += rq[tid+st]; }
        __syncthreads();
    }
    if (tid == 0) { g_ps[b] = rs[0]; g_pq[b] = rq[0]; }
}

__global__ void recon_out(float* __restrict__ out)
{
    int idx = blockIdx.x * blockDim.x + threadIdx.x;
    out[idx] = sigmoidf(g_aD2[0] * g_d2[idx] + g_bD2[0]);
}

// ---------------- host ----------------
extern "C" void kernel_launch(void* const* d_in, const int* in_sizes, int n_in,
                              void* d_out, int out_size)
{
    if (n_in < 26) return;
    const float* x      = (const float*)d_in[0];
    const float* gamma  = (const float*)d_in[1];
    const float* c1_w   = (const float*)d_in[2];
    const float* c1_b   = (const float*)d_in[3];
    const float* bn1_s  = (const float*)d_in[4];
    const float* bn1_b  = (const float*)d_in[5];
    const float* c2_w   = (const float*)d_in[6];
    const float* c2_b   = (const float*)d_in[7];
    const float* bn2_s  = (const float*)d_in[8];
    const float* bn2_b  = (const float*)d_in[9];
    const float* lat_w  = (const float*)d_in[10];
    const float* lat_b  = (const float*)d_in[11];
    const float* bnl_s  = (const float*)d_in[12];
    const float* bnl_b  = (const float*)d_in[13];
    const float* fc_w   = (const float*)d_in[14];
    const float* fc_b   = (const float*)d_in[15];
    const float* bnf_s  = (const float*)d_in[16];
    const float* bnf_b  = (const float*)d_in[17];
    const float* d1_w   = (const float*)d_in[18];
    const float* d1_b   = (const float*)d_in[19];
    const float* bnd1_s = (const float*)d_in[20];
    const float* bnd1_b = (const float*)d_in[21];
    const float* d2_w   = (const float*)d_in[22];
    const float* d2_b   = (const float*)d_in[23];
    const float* bnd2_s = (const float*)d_in[24];
    const float* bnd2_b = (const float*)d_in[25];

    float* out     = (float*)d_out;
    float* o_recon = out + OFF_RECON;
    float* o_proto = out + OFF_PROTO;
    float* o_rad   = out + OFF_RAD;
    float* o_lat   = out + OFF_LAT;

    void *p_h2, *p_xrec, *p_gpart, *p_fc;
    cudaGetSymbolAddress(&p_h2,    g_h2);
    cudaGetSymbolAddress(&p_xrec,  g_xrec);
    cudaGetSymbolAddress(&p_gpart, g_gpart);
    cudaGetSymbolAddress(&p_fc,    g_fc);

    void *p_a1, *p_b1, *p_a2, *p_b2, *p_aL, *p_bL, *p_aF, *p_bF, *p_aD1, *p_bD1, *p_aD2, *p_bD2;
    cudaGetSymbolAddress(&p_a1,  g_a1);   cudaGetSymbolAddress(&p_b1,  g_b1);
    cudaGetSymbolAddress(&p_a2,  g_a2);   cudaGetSymbolAddress(&p_b2,  g_b2);
    cudaGetSymbolAddress(&p_aL,  g_aL);   cudaGetSymbolAddress(&p_bL,  g_bL);
    cudaGetSymbolAddress(&p_aF,  g_aF);   cudaGetSymbolAddress(&p_bF,  g_bF);
    cudaGetSymbolAddress(&p_aD1, g_aD1);  cudaGetSymbolAddress(&p_bD1, g_bD1);
    cudaGetSymbolAddress(&p_aD2, g_aD2);  cudaGetSymbolAddress(&p_bD2, g_bD2);

    // ---- encoder ----
    conv1_kernel<<<BB, 256>>>(x, c1_w, c1_b);                       // + h1 stats (layout B)
    bn_finalize3<<<64, 512>>>(BB, 4, 256, 1.f/(BB*196.f), bn1_s, bn1_b, (float*)p_a1, (float*)p_b1);

    conv2_kernel<<<BB, 112>>>(c2_w, c2_b);                          // + h2 stats (layout B)
    bn_finalize3<<<128, 512>>>(BB, 7, 896, 1.f/(BB*49.f), bn2_s, bn2_b, (float*)p_a2, (float*)p_b2);

    // latent GEMM (split-K=4), bn2+leaky fused into A load
    sgemm_nt<1><<<dim3(LAT/128, BB/128, 4), 256>>>(
        (const float*)p_h2, lat_w, nullptr, (float*)p_gpart,
        BB, LAT, FLATD, FLATD/4, (const float*)p_a2, (const float*)p_b2);
    combine_lat_stats<<<32, 512>>>(lat_b);                          // + lat stats (layout A, S=32)
    bn_finalize2<<<LAT, 128>>>(32, 1.f/(float)BB, bnl_s, bnl_b, (float*)p_aL, (float*)p_bL);
    latent_act<<<(BB*LAT + 255)/256, 256>>>(o_lat);

    // ---- prototypes / radius ----
    proto_kernel<<<WAYS, LAT>>>(o_lat, o_proto);
    attn_radius_kernel<<<WAYS, 64>>>(o_proto, o_rad);
    recon_latent<<<(BB*LAT + 255)/256, 256>>>(o_lat, o_rad, gamma);

    // ---- decoder ----
    sgemm_nt<0><<<dim3(FLATD/128, BB/128, 1), 256>>>(               // + fc stats (layout A, S=16)
        (const float*)p_xrec, fc_w, fc_b, (float*)p_fc,
        BB, FLATD, LAT, LAT, nullptr, nullptr);
    bn_finalize2<<<FLATD, 128>>>(16, 1.f/(float)BB, bnf_s, bnf_b, (float*)p_aF, (float*)p_bF);

    deconv1_kernel<<<BB, 224>>>(d1_w, d1_b);                        // + d1 stats (layout B)
    bn_finalize3<<<64, 512>>>(BB, 14, 896, 1.f/(BB*196.f), bnd1_s, bnd1_b, (float*)p_aD1, (float*)p_bD1);

    deconv2_kernel<<<BB, 784>>>(d2_w, d2_b);                        // + d2 stats (layout A, S=2048)
    bn_finalize2<<<1, 128>>>(2048, 1.f/(BB*784.f), bnd2_s, bnd2_b, (float*)p_aD2, (float*)p_bD2);

    recon_out<<<BB*784/256, 256>>>(o_recon);
}

// round 14
// speedup vs baseline: 1.0296x; 1.0296x over previous
#include <cuda_runtime.h>

// ---------------- problem constants ----------------
#define BB     2048
#define WAYS   64
#define SHOT   32
#define LAT    512
#define FLATD  6272
#define EPSBN  1e-5f
#define SLOPE  0.2f

#define OFF_RECON 0
#define OFF_PROTO 1605632
#define OFF_RAD   1638400
#define OFF_LAT   1671168

// ---------------- scratch (device globals; no runtime alloc) ----------------
__device__ float g_h1 [BB*64*196];   // conv1 raw
__device__ float g_h2 [BB*128*49];   // conv2 raw
__device__ float g_lat[BB*LAT];      // latent pre-BN
__device__ float g_xrec[BB*LAT];     // shifted latent
__device__ float g_fc [BB*FLATD];    // fc raw
__device__ float g_d1 [BB*64*196];   // deconv1 raw
__device__ float g_d2 [BB*784];      // deconv2 raw
__device__ float g_gpart[4*BB*LAT];  // split-K partials

__device__ float g_ps[1835008];      // BN partial sums
__device__ float g_pq[1835008];      // BN partial sumsq

__device__ float g_a1[64],  g_b1[64];
__device__ float g_a2[128], g_b2[128];
__device__ float g_aL[LAT], g_bL[LAT];
__device__ float g_aF[FLATD], g_bF[FLATD];
__device__ float g_aD1[64], g_bD1[64];
__device__ float g_aD2[1],  g_bD2[1];

__device__ __forceinline__ float leakyf(float v){ return v >= 0.f ? v : SLOPE*v; }
__device__ __forceinline__ float sigmoidf(float v){ return 1.f/(1.f+__expf(-v)); }

// ---------------- BN finalize, layout A: g_ps[c*S + i] ----------------
__global__ void bn_finalize2(int S, float invN,
                             const float* __restrict__ scale, const float* __restrict__ bias,
                             float* __restrict__ ga, float* __restrict__ gb)
{
    int c = blockIdx.x;
    __shared__ float rs[128], rq[128];
    float s = 0.f, q = 0.f;
    for (int i = threadIdx.x; i < S; i += 128) {
        s += g_ps[(size_t)c*S + i];
        q += g_pq[(size_t)c*S + i];
    }
    rs[threadIdx.x] = s; rq[threadIdx.x] = q;
    __syncthreads();
    for (int st = 64; st > 0; st >>= 1) {
        if (threadIdx.x < st) { rs[threadIdx.x] += rs[threadIdx.x+st]; rq[threadIdx.x] += rq[threadIdx.x+st]; }
        __syncthreads();
    }
    if (threadIdx.x == 0) {
        float m = rs[0] * invN;
        float v = rq[0] * invN - m * m;
        float inv = rsqrtf(v + EPSBN);
        float a = scale[c] * inv;
        ga[c] = a;
        gb[c] = bias[c] - m * a;
    }
}

// ---------------- BN finalize, layout B: g_ps[b*stride + c*P + p] — 512 threads ----------------
__global__ void __launch_bounds__(512) bn_finalize3(int nb, int P, int stride, float invN,
                             const float* __restrict__ scale, const float* __restrict__ bias,
                             float* __restrict__ ga, float* __restrict__ gb)
{
    int c = blockIdx.x;
    __shared__ float rs[512], rq[512];
    float s = 0.f, q = 0.f;
    int n = nb * P;
    for (int i = threadIdx.x; i < n; i += 512) {
        int b = i / P, p = i % P;
        size_t idx = (size_t)b*stride + c*P + p;
        s += g_ps[idx];
        q += g_pq[idx];
    }
    rs[threadIdx.x] = s; rq[threadIdx.x] = q;
    __syncthreads();
    for (int st = 256; st > 0; st >>= 1) {
        if (threadIdx.x < st) { rs[threadIdx.x] += rs[threadIdx.x+st]; rq[threadIdx.x] += rq[threadIdx.x+st]; }
        __syncthreads();
    }
    if (threadIdx.x == 0) {
        float m = rs[0] * invN;
        float v = rq[0] * invN - m * m;
        float inv = rsqrtf(v + EPSBN);
        float a = scale[c] * inv;
        ga[c] = a;
        gb[c] = bias[c] - m * a;
    }
}

// ---------------- conv1: [B,1,28,28] -> [B,64,14,14], register-stationary + free stats ----------------
__global__ void __launch_bounds__(256) conv1_kernel(const float* __restrict__ x,
                             const float* __restrict__ w, const float* __restrict__ bias)
{
    int b = blockIdx.x;
    __shared__ float sx[784];
    __shared__ float sw[1024];
    int tid = threadIdx.x;
    for (int i = tid; i < 784;  i += 256) sx[i] = x[b*784 + i];
    for (int i = tid; i < 1024; i += 256) sw[i] = w[i];
    __syncthreads();

    int c = tid >> 2, qd = tid & 3;
    float bb = bias[c];
    const float* wc = &sw[c*16];
    float* dst = &g_h1[(size_t)(b*64 + c)*196];
    float s = 0.f, q = 0.f;
    #pragma unroll 7
    for (int t = 0; t < 49; t++) {
        int pix = qd*49 + t;
        int oy = pix / 14, ox = pix % 14;
        float acc = bb;
        #pragma unroll
        for (int ky = 0; ky < 4; ky++) {
            int iy = 2*oy + ky - 1;
            if ((unsigned)iy < 28u) {
                #pragma unroll
                for (int kx = 0; kx < 4; kx++) {
                    int ix = 2*ox + kx - 1;
                    if ((unsigned)ix < 28u)
                        acc += sx[iy*28+ix] * wc[ky*4+kx];
                }
            }
        }
        dst[pix] = acc;
        s += acc; q += acc*acc;
    }
    g_ps[(size_t)b*256 + tid] = s;   // layout B: stride=256, P=4
    g_pq[(size_t)b*256 + tid] = q;
}

// ---------------- conv2: [B,64,14,14] -> [B,128,7,7], bn1+leaky fused, free stats ----------------
// 224 threads: (channel-group-of-4, oy); partials written straight to global.
__global__ void __launch_bounds__(224) conv2_kernel(const float* __restrict__ w,
                                                    const float* __restrict__ bias)
{
    int b = blockIdx.x;
    __shared__ float sin2[32*196];   // 25088 B
    int tid = threadIdx.x;
    int cg = tid / 7, oy = tid % 7;
    int co = 4*cg;
    float acc[4][7];
    #pragma unroll
    for (int u = 0; u < 4; u++) {
        float bb = bias[co+u];
        #pragma unroll
        for (int j = 0; j < 7; j++) acc[u][j] = bb;
    }

    for (int cc = 0; cc < 64; cc += 32) {
        __syncthreads();   // previous chunk fully consumed
        const float* src = g_h1 + ((size_t)b*64 + cc)*196;
        for (int i = tid; i < 32*196; i += 224) {
            int c = cc + i/196;
            sin2[i] = leakyf(g_a1[c]*src[i] + g_b1[c]);
        }
        __syncthreads();
        for (int ci = 0; ci < 32; ci++) {
            const float* inc = &sin2[ci*196];
            int cig = cc + ci;
            #pragma unroll
            for (int ky = 0; ky < 4; ky++) {
                int iy = 2*oy + ky - 1;
                if ((unsigned)iy >= 14u) continue;
                float rE[16];
                rE[0] = 0.f; rE[15] = 0.f;
                #pragma unroll
                for (int t = 0; t < 14; t++) rE[t+1] = inc[iy*14 + t];
                float4 wv[4];
                #pragma unroll
                for (int u = 0; u < 4; u++)
                    wv[u] = *reinterpret_cast<const float4*>(&w[(size_t)((co+u)*64 + cig)*16 + ky*4]);
                #pragma unroll
                for (int ox = 0; ox < 7; ox++) {
                    int p = 2*ox;
                    float e0 = rE[p], e1 = rE[p+1], e2 = rE[p+2], e3 = rE[p+3];
                    #pragma unroll
                    for (int u = 0; u < 4; u++)
                        acc[u][ox] += e0*wv[u].x + e1*wv[u].y + e2*wv[u].z + e3*wv[u].w;
                }
            }
        }
    }
    #pragma unroll
    for (int u = 0; u < 4; u++) {
        float s = 0.f, q = 0.f;
        #pragma unroll
        for (int ox = 0; ox < 7; ox++) {
            float v = acc[u][ox];
            g_h2[(size_t)(b*128 + co+u)*49 + oy*7 + ox] = v;
            s += v; q += v*v;
        }
        g_ps[(size_t)b*896 + (co+u)*7 + oy] = s;   // layout B: stride=896, P=7
        g_pq[(size_t)b*896 + (co+u)*7 + oy] = q;
    }
}

// ---------------- SGEMM NT: C[M,N] = act(A)[M,K] * W[N,K]^T (+bias) ----------------
// MODE 1: latent GEMM, A gets bn2-affine + leaky (c=k/49), split-K partial output.
// MODE 0: fc GEMM, bias added, fused per-column BN partial stats (layout A, S=16).
template<int MODE>
__global__ void __launch_bounds__(256) sgemm_nt(
    const float* __restrict__ A, const float* __restrict__ W,
    const float* __restrict__ bias, float* __restrict__ out,
    int M, int N, int K, int Ktile,
    const float* __restrict__ ca, const float* __restrict__ cb)
{
    __shared__ float As[16][128];
    __shared__ float Bs[16][128];
    const int tid = threadIdx.x;
    const int bm = blockIdx.y * 128;
    const int bn = blockIdx.x * 128;
    const int lr = tid >> 2;
    const int lc = (tid & 3) << 2;
    const int tm = (tid >> 4) << 3;
    const int tn = (tid & 15) << 3;
    float acc[8][8];
    #pragma unroll
    for (int i = 0; i < 8; i++)
        #pragma unroll
        for (int j = 0; j < 8; j++) acc[i][j] = 0.f;

    const int k0beg = blockIdx.z * Ktile;
    for (int k0 = k0beg; k0 < k0beg + Ktile; k0 += 16) {
        #pragma unroll
        for (int h = 0; h < 2; h++) {
            int row = bm + lr + (h << 6);
            float4 v = *reinterpret_cast<const float4*>(A + (size_t)row*K + k0 + lc);
            if (MODE == 1) {
                int kb = k0 + lc;
                int c0 = (kb  )/49, c1 = (kb+1)/49, c2 = (kb+2)/49, c3 = (kb+3)/49;
                v.x = leakyf(ca[c0]*v.x + cb[c0]);
                v.y = leakyf(ca[c1]*v.y + cb[c1]);
                v.z = leakyf(ca[c2]*v.z + cb[c2]);
                v.w = leakyf(ca[c3]*v.w + cb[c3]);
            }
            As[lc+0][lr+(h<<6)] = v.x; As[lc+1][lr+(h<<6)] = v.y;
            As[lc+2][lr+(h<<6)] = v.z; As[lc+3][lr+(h<<6)] = v.w;

            int wrow = bn + lr + (h << 6);
            float4 wv = *reinterpret_cast<const float4*>(W + (size_t)wrow*K + k0 + lc);
            Bs[lc+0][lr+(h<<6)] = wv.x; Bs[lc+1][lr+(h<<6)] = wv.y;
            Bs[lc+2][lr+(h<<6)] = wv.z; Bs[lc+3][lr+(h<<6)] = wv.w;
        }
        __syncthreads();
        #pragma unroll
        for (int kk = 0; kk < 16; kk++) {
            float a[8], bb[8];
            #pragma unroll
            for (int i = 0; i < 8; i++) a[i]  = As[kk][tm+i];
            #pragma unroll
            for (int j = 0; j < 8; j++) bb[j] = Bs[kk][tn+j];
            #pragma unroll
            for (int i = 0; i < 8; i++)
                #pragma unroll
                for (int j = 0; j < 8; j++) acc[i][j] += a[i]*bb[j];
        }
        __syncthreads();
    }

    if (MODE == 0) {
        float cs[8], cq[8];
        #pragma unroll
        for (int j = 0; j < 8; j++) { cs[j] = 0.f; cq[j] = 0.f; }
        #pragma unroll
        for (int i = 0; i < 8; i++) {
            float* o = out + (size_t)(bm+tm+i)*N + bn;
            #pragma unroll
            for (int j = 0; j < 8; j++) {
                float v = acc[i][j] + bias[bn+tn+j];
                o[tn+j] = v;
                cs[j] += v; cq[j] += v*v;
            }
        }
        // reduce per-column partials through As/Bs (free after last loop sync)
        int g = tid >> 4;
        #pragma unroll
        for (int j = 0; j < 8; j++) { As[g][tn+j] = cs[j]; Bs[g][tn+j] = cq[j]; }
        __syncthreads();
        if (tid < 128) {
            float s = 0.f, q = 0.f;
            #pragma unroll
            for (int g2 = 0; g2 < 16; g2++) { s += As[g2][tid]; q += Bs[g2][tid]; }
            g_ps[(size_t)(bn+tid)*16 + blockIdx.y] = s;
            g_pq[(size_t)(bn+tid)*16 + blockIdx.y] = q;
        }
    } else {
        float* P = out + (size_t)blockIdx.z * M * N;
        #pragma unroll
        for (int i = 0; i < 8; i++) {
            float* o = P + (size_t)(bm+tm+i)*N + bn;
            #pragma unroll
            for (int j = 0; j < 8; j++) o[tn+j] = acc[i][j];
        }
    }
}

// ---------------- combine split-K partials + bias, fused latent BN stats (layout A, S=32) ----------------
__global__ void __launch_bounds__(512) combine_lat_stats(const float* __restrict__ bias)
{
    int c = threadIdx.x;
    int s = blockIdx.x;
    float bc = bias[c];
    float sum = 0.f, sq = 0.f;
    for (int r = s*64; r < s*64 + 64; r++) {
        size_t idx = (size_t)r*LAT + c;
        float v = g_gpart[idx] + g_gpart[(size_t)BB*LAT + idx]
                + g_gpart[2*(size_t)BB*LAT + idx] + g_gpart[3*(size_t)BB*LAT + idx] + bc;
        g_lat[idx] = v;
        sum += v; sq += v*v;
    }
    g_ps[(size_t)c*32 + s] = sum;
    g_pq[(size_t)c*32 + s] = sq;
}

// ---------------- fused latent activation + prototypes ----------------
// grid 64 (= w), 512 threads (= latent column). Each block handles its 32 shot rows:
// writes sigmoid-activated xlat and the per-class prototype mean (same sum order as before).
__global__ void __launch_bounds__(512) latent_act_proto(float* __restrict__ xlat,
                                                        float* __restrict__ proto)
{
    int w = blockIdx.x;
    int c = threadIdx.x;
    float a = g_aL[c], bo = g_bL[c];
    float s = 0.f;
    #pragma unroll
    for (int j = 0; j < SHOT; j++) {
        size_t idx = (size_t)(w*SHOT + j)*LAT + c;
        float v = sigmoidf(a*g_lat[idx] + bo);
        xlat[idx] = v;
        s += v;
    }
    proto[w*LAT + c] = s * (1.f/SHOT);
}

__global__ void attn_radius_kernel(const float* __restrict__ proto, float* __restrict__ radius)
{
    int i = blockIdx.x;
    int tid = threadIdx.x;   // 64
    __shared__ float spi[LAT];
    __shared__ float att[WAYS];
    for (int l = tid; l < LAT; l += 64) spi[l] = proto[i*LAT + l];
    __syncthreads();
    float dot = 0.f;
    const float* pj = proto + tid*LAT;
    for (int l = 0; l < LAT; l++) dot += spi[l] * pj[l];
    att[tid] = dot;
    __syncthreads();
    float mx = -1e30f;
    for (int j = 0; j < WAYS; j++) mx = fmaxf(mx, att[j]);
    float ex = __expf(att[tid] - mx);
    __syncthreads();
    att[tid] = ex;
    __syncthreads();
    float sum = 0.f;
    for (int j = 0; j < WAYS; j++) sum += att[j];
    float inv = 1.f / sum;
    for (int r = 0; r < 8; r++) {
        int l = tid + (r << 6);
        float accv = 0.f;
        for (int j = 0; j < WAYS; j++) accv += att[j] * proto[j*LAT + l];
        radius[i*LAT + l] = spi[l] - accv * inv;
    }
}

__global__ void recon_latent(const float* __restrict__ xlat, const float* __restrict__ radius,
                             const float* __restrict__ gamma)
{
    int idx = blockIdx.x * blockDim.x + threadIdx.x;
    if (idx >= BB*LAT) return;
    int c = idx & (LAT-1);
    int m = idx >> 9;
    int w = m >> 5;
    g_xrec[idx] = xlat[idx] + radius[(w << 9) + c] * gamma[0];
}

// ---------------- deconv1: [B,128,7,7] -> [B,64,14,14], bnf fused, free stats ----------------
__global__ void __launch_bounds__(224) deconv1_kernel(const float* __restrict__ w,
                                                      const float* __restrict__ bias)
{
    int b = blockIdx.x;
    __shared__ float sin1[128*49];   // 25088 B
    const float* src = g_fc + (size_t)b * FLATD;
    int tid = threadIdx.x;
    for (int i = tid; i < FLATD; i += 224)
        sin1[i] = g_aF[i] * src[i] + g_bF[i];
    __syncthreads();
    int cg = tid / 14, oy = tid % 14;
    int co = 4*cg;
    float acc[4][14];
    #pragma unroll
    for (int u = 0; u < 4; u++) {
        float bb = bias[co+u];
        #pragma unroll
        for (int j = 0; j < 14; j++) acc[u][j] = bb;
    }
    int kyp = oy & 1;
    for (int ci = 0; ci < 128; ci++) {
        const float* inc = &sin1[ci*49];
        #pragma unroll
        for (int kyi = 0; kyi < 2; kyi++) {
            int ky = kyp + 2*kyi;
            int iy = (oy + ky - 2) >> 1;
            if ((unsigned)iy >= 7u) continue;
            float r[7];
            #pragma unroll
            for (int t = 0; t < 7; t++) r[t] = inc[iy*7 + t];
            float wr[4][4];
            #pragma unroll
            for (int u = 0; u < 4; u++) {
                float4 q = *reinterpret_cast<const float4*>(&w[(size_t)(ci*64 + co+u)*16 + (3-ky)*4]);
                wr[u][0] = q.w; wr[u][1] = q.z; wr[u][2] = q.y; wr[u][3] = q.x;
            }
            #pragma unroll
            for (int ox = 0; ox < 14; ox++) {
                int kxp = ox & 1;
                #pragma unroll
                for (int kxi = 0; kxi < 2; kxi++) {
                    int kx = kxp + 2*kxi;
                    int ix = (ox + kx - 2) >> 1;
                    if ((unsigned)ix < 7u) {
                        float rv = r[ix];
                        #pragma unroll
                        for (int u = 0; u < 4; u++)
                            acc[u][ox] += rv * wr[u][kx];
                    }
                }
            }
        }
    }
    #pragma unroll
    for (int u = 0; u < 4; u++) {
        float s = 0.f, q = 0.f;
        #pragma unroll
        for (int ox = 0; ox < 14; ox++) {
            float v = acc[u][ox];
            g_d1[(size_t)(b*64 + co+u)*196 + oy*14 + ox] = v;
            s += v; q += v*v;
        }
        g_ps[(size_t)b*896 + (co+u)*14 + oy] = s;   // layout B: stride=896, P=14
        g_pq[(size_t)b*896 + (co+u)*14 + oy] = q;
    }
}

// ---------------- deconv2: [B,64,14,14] -> [B,1,28,28], bnd1+leaky fused, fused stats ----------------
__global__ void __launch_bounds__(784) deconv2_kernel(const float* __restrict__ w,
                                                      const float* __restrict__ bias)
{
    int b = blockIdx.x;
    __shared__ float sin3[32*196];   // 25088 B
    __shared__ float swt[1024];
    __shared__ float rs[784], rq[784];
    int tid = threadIdx.x;
    for (int i = tid; i < 1024; i += 784) swt[i] = w[i];

    int oy = tid / 28, ox = tid % 28;
    int kyp = oy & 1, kxp = ox & 1;
    int iy0 = (oy + kyp - 2) >> 1;
    int iy1 = (oy + kyp) >> 1;
    int ix0 = (ox + kxp - 2) >> 1;
    int ix1 = (ox + kxp) >> 1;
    bool vy0 = (unsigned)iy0 < 14u, vy1 = (unsigned)iy1 < 14u;
    bool vx0 = (unsigned)ix0 < 14u, vx1 = (unsigned)ix1 < 14u;
    int o00 = (3-kyp)*4 + (3-kxp);
    int o01 = (3-kyp)*4 + (1-kxp);
    int o10 = (1-kyp)*4 + (3-kxp);
    int o11 = (1-kyp)*4 + (1-kxp);
    float acc = bias[0];

    for (int cc = 0; cc < 64; cc += 32) {
        __syncthreads();
        const float* src = g_d1 + ((size_t)b*64 + cc)*196;
        for (int i = tid; i < 32*196; i += 784) {
            int c = cc + i/196;
            sin3[i] = leakyf(g_aD1[c]*src[i] + g_bD1[c]);
        }
        __syncthreads();
        for (int ci = 0; ci < 32; ci++) {
            const float* sc = &sin3[ci*196];
            const float* wb = &swt[(cc+ci)*16];
            if (vy0 && vx0) acc += sc[iy0*14+ix0] * wb[o00];
            if (vy0 && vx1) acc += sc[iy0*14+ix1] * wb[o01];
            if (vy1 && vx0) acc += sc[iy1*14+ix0] * wb[o10];
            if (vy1 && vx1) acc += sc[iy1*14+ix1] * wb[o11];
        }
    }
    g_d2[(size_t)b*784 + tid] = acc;

    // fused single-channel stats: block reduction of 784 values (layout A, c=0, S=2048)
    rs[tid] = acc; rq[tid] = acc*acc;
    __syncthreads();
    if (tid < 272) { rs[tid] += rs[tid+512]; rq[tid] += rq[tid+512]; }
    __syncthreads();
    for (int st = 256; st > 0; st >>= 1) {
        if (tid < st) { rs[tid] += rs[tid+st]; rq[tid] += rq[tid+st]; }
        __syncthreads();
    }
    if (tid == 0) { g_ps[b] = rs[0]; g_pq[b] = rq[0]; }
}

__global__ void recon_out(float* __restrict__ out)
{
    int idx = blockIdx.x * blockDim.x + threadIdx.x;
    out[idx] = sigmoidf(g_aD2[0] * g_d2[idx] + g_bD2[0]);
}

// ---------------- host ----------------
extern "C" void kernel_launch(void* const* d_in, const int* in_sizes, int n_in,
                              void* d_out, int out_size)
{
    if (n_in < 26) return;
    const float* x      = (const float*)d_in[0];
    const float* gamma  = (const float*)d_in[1];
    const float* c1_w   = (const float*)d_in[2];
    const float* c1_b   = (const float*)d_in[3];
    const float* bn1_s  = (const float*)d_in[4];
    const float* bn1_b  = (const float*)d_in[5];
    const float* c2_w   = (const float*)d_in[6];
    const float* c2_b   = (const float*)d_in[7];
    const float* bn2_s  = (const float*)d_in[8];
    const float* bn2_b  = (const float*)d_in[9];
    const float* lat_w  = (const float*)d_in[10];
    const float* lat_b  = (const float*)d_in[11];
    const float* bnl_s  = (const float*)d_in[12];
    const float* bnl_b  = (const float*)d_in[13];
    const float* fc_w   = (const float*)d_in[14];
    const float* fc_b   = (const float*)d_in[15];
    const float* bnf_s  = (const float*)d_in[16];
    const float* bnf_b  = (const float*)d_in[17];
    const float* d1_w   = (const float*)d_in[18];
    const float* d1_b   = (const float*)d_in[19];
    const float* bnd1_s = (const float*)d_in[20];
    const float* bnd1_b = (const float*)d_in[21];
    const float* d2_w   = (const float*)d_in[22];
    const float* d2_b   = (const float*)d_in[23];
    const float* bnd2_s = (const float*)d_in[24];
    const float* bnd2_b = (const float*)d_in[25];

    float* out     = (float*)d_out;
    float* o_recon = out + OFF_RECON;
    float* o_proto = out + OFF_PROTO;
    float* o_rad   = out + OFF_RAD;
    float* o_lat   = out + OFF_LAT;

    void *p_h2, *p_xrec, *p_gpart, *p_fc;
    cudaGetSymbolAddress(&p_h2,    g_h2);
    cudaGetSymbolAddress(&p_xrec,  g_xrec);
    cudaGetSymbolAddress(&p_gpart, g_gpart);
    cudaGetSymbolAddress(&p_fc,    g_fc);

    void *p_a1, *p_b1, *p_a2, *p_b2, *p_aL, *p_bL, *p_aF, *p_bF, *p_aD1, *p_bD1, *p_aD2, *p_bD2;
    cudaGetSymbolAddress(&p_a1,  g_a1);   cudaGetSymbolAddress(&p_b1,  g_b1);
    cudaGetSymbolAddress(&p_a2,  g_a2);   cudaGetSymbolAddress(&p_b2,  g_b2);
    cudaGetSymbolAddress(&p_aL,  g_aL);   cudaGetSymbolAddress(&p_bL,  g_bL);
    cudaGetSymbolAddress(&p_aF,  g_aF);   cudaGetSymbolAddress(&p_bF,  g_bF);
    cudaGetSymbolAddress(&p_aD1, g_aD1);  cudaGetSymbolAddress(&p_bD1, g_bD1);
    cudaGetSymbolAddress(&p_aD2, g_aD2);  cudaGetSymbolAddress(&p_bD2, g_bD2);

    // ---- encoder ----
    conv1_kernel<<<BB, 256>>>(x, c1_w, c1_b);                       // + h1 stats (layout B)
    bn_finalize3<<<64, 512>>>(BB, 4, 256, 1.f/(BB*196.f), bn1_s, bn1_b, (float*)p_a1, (float*)p_b1);

    conv2_kernel<<<BB, 224>>>(c2_w, c2_b);                          // + h2 stats (layout B)
    bn_finalize3<<<128, 512>>>(BB, 7, 896, 1.f/(BB*49.f), bn2_s, bn2_b, (float*)p_a2, (float*)p_b2);

    // latent GEMM (split-K=4), bn2+leaky fused into A load
    sgemm_nt<1><<<dim3(LAT/128, BB/128, 4), 256>>>(
        (const float*)p_h2, lat_w, nullptr, (float*)p_gpart,
        BB, LAT, FLATD, FLATD/4, (const float*)p_a2, (const float*)p_b2);
    combine_lat_stats<<<32, 512>>>(lat_b);                          // + lat stats (layout A, S=32)
    bn_finalize2<<<LAT, 128>>>(32, 1.f/(float)BB, bnl_s, bnl_b, (float*)p_aL, (float*)p_bL);

    // ---- prototypes / radius (latent activation fused into proto pass) ----
    latent_act_proto<<<WAYS, LAT>>>(o_lat, o_proto);
    attn_radius_kernel<<<WAYS, 64>>>(o_proto, o_rad);
    recon_latent<<<(BB*LAT + 255)/256, 256>>>(o_lat, o_rad, gamma);

    // ---- decoder ----
    sgemm_nt<0><<<dim3(FLATD/128, BB/128, 1), 256>>>(               // + fc stats (layout A, S=16)
        (const float*)p_xrec, fc_w, fc_b, (float*)p_fc,
        BB, FLATD, LAT, LAT, nullptr, nullptr);
    bn_finalize2<<<FLATD, 128>>>(16, 1.f/(float)BB, bnf_s, bnf_b, (float*)p_aF, (float*)p_bF);

    deconv1_kernel<<<BB, 224>>>(d1_w, d1_b);                        // + d1 stats (layout B)
    bn_finalize3<<<64, 512>>>(BB, 14, 896, 1.f/(BB*196.f), bnd1_s, bnd1_b, (float*)p_aD1, (float*)p_bD1);

    deconv2_kernel<<<BB, 784>>>(d2_w, d2_b);                        // + d2 stats (layout A, S=2048)
    bn_finalize2<<<1, 128>>>(2048, 1.f/(BB*784.f), bnd2_s, bnd2_b, (float*)p_aD2, (float*)p_bD2);

    recon_out<<<BB*784/256, 256>>>(o_recon);
}

// round 15
// speedup vs baseline: 1.0346x; 1.0049x over previous
#include <cuda_runtime.h>

// ---------------- problem constants ----------------
#define BB     2048
#define WAYS   64
#define SHOT   32
#define LAT    512
#define FLATD  6272
#define EPSBN  1e-5f
#define SLOPE  0.2f

#define OFF_RECON 0
#define OFF_PROTO 1605632
#define OFF_RAD   1638400
#define OFF_LAT   1671168

// ---------------- scratch (device globals; no runtime alloc) ----------------
__device__ float g_h1 [BB*64*196];   // conv1 raw
__device__ float g_h2 [BB*128*49];   // conv2 raw
__device__ float g_lat[BB*LAT];      // latent pre-BN
__device__ float g_fc [BB*FLATD];    // fc raw
__device__ float g_d1 [BB*64*196];   // deconv1 raw
__device__ float g_d2 [BB*784];      // deconv2 raw
__device__ float g_gpart[4*BB*LAT];  // split-K partials

__device__ float g_ps[1835008];      // BN partial sums
__device__ float g_pq[1835008];      // BN partial sumsq

__device__ float g_a1[64],  g_b1[64];
__device__ float g_a2[128], g_b2[128];
__device__ float g_aL[LAT], g_bL[LAT];
__device__ float g_aF[FLATD], g_bF[FLATD];
__device__ float g_aD1[64], g_bD1[64];
__device__ float g_aD2[1],  g_bD2[1];

__device__ __forceinline__ float leakyf(float v){ return v >= 0.f ? v : SLOPE*v; }
__device__ __forceinline__ float sigmoidf(float v){ return 1.f/(1.f+__expf(-v)); }

// ---------------- BN finalize, layout A: g_ps[c*S + i] ----------------
__global__ void bn_finalize2(int S, float invN,
                             const float* __restrict__ scale, const float* __restrict__ bias,
                             float* __restrict__ ga, float* __restrict__ gb)
{
    int c = blockIdx.x;
    __shared__ float rs[128], rq[128];
    float s = 0.f, q = 0.f;
    for (int i = threadIdx.x; i < S; i += 128) {
        s += g_ps[(size_t)c*S + i];
        q += g_pq[(size_t)c*S + i];
    }
    rs[threadIdx.x] = s; rq[threadIdx.x] = q;
    __syncthreads();
    for (int st = 64; st > 0; st >>= 1) {
        if (threadIdx.x < st) { rs[threadIdx.x] += rs[threadIdx.x+st]; rq[threadIdx.x] += rq[threadIdx.x+st]; }
        __syncthreads();
    }
    if (threadIdx.x == 0) {
        float m = rs[0] * invN;
        float v = rq[0] * invN - m * m;
        float inv = rsqrtf(v + EPSBN);
        float a = scale[c] * inv;
        ga[c] = a;
        gb[c] = bias[c] - m * a;
    }
}

// ---------------- BN finalize, layout B: g_ps[b*stride + c*P + p] — 512 threads ----------------
__global__ void __launch_bounds__(512) bn_finalize3(int nb, int P, int stride, float invN,
                             const float* __restrict__ scale, const float* __restrict__ bias,
                             float* __restrict__ ga, float* __restrict__ gb)
{
    int c = blockIdx.x;
    __shared__ float rs[512], rq[512];
    float s = 0.f, q = 0.f;
    int n = nb * P;
    for (int i = threadIdx.x; i < n; i += 512) {
        int b = i / P, p = i % P;
        size_t idx = (size_t)b*stride + c*P + p;
        s += g_ps[idx];
        q += g_pq[idx];
    }
    rs[threadIdx.x] = s; rq[threadIdx.x] = q;
    __syncthreads();
    for (int st = 256; st > 0; st >>= 1) {
        if (threadIdx.x < st) { rs[threadIdx.x] += rs[threadIdx.x+st]; rq[threadIdx.x] += rq[threadIdx.x+st]; }
        __syncthreads();
    }
    if (threadIdx.x == 0) {
        float m = rs[0] * invN;
        float v = rq[0] * invN - m * m;
        float inv = rsqrtf(v + EPSBN);
        float a = scale[c] * inv;
        ga[c] = a;
        gb[c] = bias[c] - m * a;
    }
}

// ---------------- conv1: [B,1,28,28] -> [B,64,14,14], register-stationary + free stats ----------------
__global__ void __launch_bounds__(256) conv1_kernel(const float* __restrict__ x,
                             const float* __restrict__ w, const float* __restrict__ bias)
{
    int b = blockIdx.x;
    __shared__ float sx[784];
    __shared__ float sw[1024];
    int tid = threadIdx.x;
    for (int i = tid; i < 784;  i += 256) sx[i] = x[b*784 + i];
    for (int i = tid; i < 1024; i += 256) sw[i] = w[i];
    __syncthreads();

    int c = tid >> 2, qd = tid & 3;
    float bb = bias[c];
    const float* wc = &sw[c*16];
    float* dst = &g_h1[(size_t)(b*64 + c)*196];
    float s = 0.f, q = 0.f;
    #pragma unroll 7
    for (int t = 0; t < 49; t++) {
        int pix = qd*49 + t;
        int oy = pix / 14, ox = pix % 14;
        float acc = bb;
        #pragma unroll
        for (int ky = 0; ky < 4; ky++) {
            int iy = 2*oy + ky - 1;
            if ((unsigned)iy < 28u) {
                #pragma unroll
                for (int kx = 0; kx < 4; kx++) {
                    int ix = 2*ox + kx - 1;
                    if ((unsigned)ix < 28u)
                        acc += sx[iy*28+ix] * wc[ky*4+kx];
                }
            }
        }
        dst[pix] = acc;
        s += acc; q += acc*acc;
    }
    g_ps[(size_t)b*256 + tid] = s;   // layout B: stride=256, P=4
    g_pq[(size_t)b*256 + tid] = q;
}

// ---------------- conv2: [B,64,14,14] -> [B,128,7,7], bn1+leaky fused, free stats ----------------
__global__ void __launch_bounds__(224) conv2_kernel(const float* __restrict__ w,
                                                    const float* __restrict__ bias)
{
    int b = blockIdx.x;
    __shared__ float sin2[32*196];   // 25088 B
    int tid = threadIdx.x;
    int cg = tid / 7, oy = tid % 7;
    int co = 4*cg;
    float acc[4][7];
    #pragma unroll
    for (int u = 0; u < 4; u++) {
        float bb = bias[co+u];
        #pragma unroll
        for (int j = 0; j < 7; j++) acc[u][j] = bb;
    }

    for (int cc = 0; cc < 64; cc += 32) {
        __syncthreads();   // previous chunk fully consumed
        const float* src = g_h1 + ((size_t)b*64 + cc)*196;
        for (int i = tid; i < 32*196; i += 224) {
            int c = cc + i/196;
            sin2[i] = leakyf(g_a1[c]*src[i] + g_b1[c]);
        }
        __syncthreads();
        for (int ci = 0; ci < 32; ci++) {
            const float* inc = &sin2[ci*196];
            int cig = cc + ci;
            #pragma unroll
            for (int ky = 0; ky < 4; ky++) {
                int iy = 2*oy + ky - 1;
                if ((unsigned)iy >= 14u) continue;
                float rE[16];
                rE[0] = 0.f; rE[15] = 0.f;
                #pragma unroll
                for (int t = 0; t < 14; t++) rE[t+1] = inc[iy*14 + t];
                float4 wv[4];
                #pragma unroll
                for (int u = 0; u < 4; u++)
                    wv[u] = *reinterpret_cast<const float4*>(&w[(size_t)((co+u)*64 + cig)*16 + ky*4]);
                #pragma unroll
                for (int ox = 0; ox < 7; ox++) {
                    int p = 2*ox;
                    float e0 = rE[p], e1 = rE[p+1], e2 = rE[p+2], e3 = rE[p+3];
                    #pragma unroll
                    for (int u = 0; u < 4; u++)
                        acc[u][ox] += e0*wv[u].x + e1*wv[u].y + e2*wv[u].z + e3*wv[u].w;
                }
            }
        }
    }
    #pragma unroll
    for (int u = 0; u < 4; u++) {
        float s = 0.f, q = 0.f;
        #pragma unroll
        for (int ox = 0; ox < 7; ox++) {
            float v = acc[u][ox];
            g_h2[(size_t)(b*128 + co+u)*49 + oy*7 + ox] = v;
            s += v; q += v*v;
        }
        g_ps[(size_t)b*896 + (co+u)*7 + oy] = s;   // layout B: stride=896, P=7
        g_pq[(size_t)b*896 + (co+u)*7 + oy] = q;
    }
}

// ---------------- SGEMM NT: C[M,N] = act(A)[M,K] * W[N,K]^T (+bias) ----------------
// MODE 1: latent GEMM, A gets bn2-affine + leaky (c=k/49), split-K partial output.
// MODE 0: fc GEMM; A = xlat + radius*gamma fused on load; bias + fused BN stats (layout A, S=16).
template<int MODE>
__global__ void __launch_bounds__(256) sgemm_nt(
    const float* __restrict__ A, const float* __restrict__ W,
    const float* __restrict__ bias, float* __restrict__ out,
    int M, int N, int K, int Ktile,
    const float* __restrict__ ca, const float* __restrict__ cb,
    const float* __restrict__ radius, const float* __restrict__ gamma)
{
    __shared__ float As[16][128];
    __shared__ float Bs[16][128];
    const int tid = threadIdx.x;
    const int bm = blockIdx.y * 128;
    const int bn = blockIdx.x * 128;
    const int lr = tid >> 2;
    const int lc = (tid & 3) << 2;
    const int tm = (tid >> 4) << 3;
    const int tn = (tid & 15) << 3;
    float acc[8][8];
    #pragma unroll
    for (int i = 0; i < 8; i++)
        #pragma unroll
        for (int j = 0; j < 8; j++) acc[i][j] = 0.f;

    float gm = (MODE == 0) ? gamma[0] : 0.f;

    const int k0beg = blockIdx.z * Ktile;
    for (int k0 = k0beg; k0 < k0beg + Ktile; k0 += 16) {
        #pragma unroll
        for (int h = 0; h < 2; h++) {
            int row = bm + lr + (h << 6);
            float4 v = *reinterpret_cast<const float4*>(A + (size_t)row*K + k0 + lc);
            if (MODE == 1) {
                int kb = k0 + lc;
                int c0 = (kb  )/49, c1 = (kb+1)/49, c2 = (kb+2)/49, c3 = (kb+3)/49;
                v.x = leakyf(ca[c0]*v.x + cb[c0]);
                v.y = leakyf(ca[c1]*v.y + cb[c1]);
                v.z = leakyf(ca[c2]*v.z + cb[c2]);
                v.w = leakyf(ca[c3]*v.w + cb[c3]);
            } else {
                int wdx = row >> 5;   // class index (row / SHOT)
                float4 r = *reinterpret_cast<const float4*>(radius + (wdx << 9) + k0 + lc);
                v.x += r.x * gm; v.y += r.y * gm; v.z += r.z * gm; v.w += r.w * gm;
            }
            As[lc+0][lr+(h<<6)] = v.x; As[lc+1][lr+(h<<6)] = v.y;
            As[lc+2][lr+(h<<6)] = v.z; As[lc+3][lr+(h<<6)] = v.w;

            int wrow = bn + lr + (h << 6);
            float4 wv = *reinterpret_cast<const float4*>(W + (size_t)wrow*K + k0 + lc);
            Bs[lc+0][lr+(h<<6)] = wv.x; Bs[lc+1][lr+(h<<6)] = wv.y;
            Bs[lc+2][lr+(h<<6)] = wv.z; Bs[lc+3][lr+(h<<6)] = wv.w;
        }
        __syncthreads();
        #pragma unroll
        for (int kk = 0; kk < 16; kk++) {
            float a[8], bb[8];
            #pragma unroll
            for (int i = 0; i < 8; i++) a[i]  = As[kk][tm+i];
            #pragma unroll
            for (int j = 0; j < 8; j++) bb[j] = Bs[kk][tn+j];
            #pragma unroll
            for (int i = 0; i < 8; i++)
                #pragma unroll
                for (int j = 0; j < 8; j++) acc[i][j] += a[i]*bb[j];
        }
        __syncthreads();
    }

    if (MODE == 0) {
        float cs[8], cq[8];
        #pragma unroll
        for (int j = 0; j < 8; j++) { cs[j] = 0.f; cq[j] = 0.f; }
        #pragma unroll
        for (int i = 0; i < 8; i++) {
            float* o = out + (size_t)(bm+tm+i)*N + bn;
            #pragma unroll
            for (int j = 0; j < 8; j++) {
                float v = acc[i][j] + bias[bn+tn+j];
                o[tn+j] = v;
                cs[j] += v; cq[j] += v*v;
            }
        }
        // reduce per-column partials through As/Bs (free after last loop sync)
        int g = tid >> 4;
        #pragma unroll
        for (int j = 0; j < 8; j++) { As[g][tn+j] = cs[j]; Bs[g][tn+j] = cq[j]; }
        __syncthreads();
        if (tid < 128) {
            float s = 0.f, q = 0.f;
            #pragma unroll
            for (int g2 = 0; g2 < 16; g2++) { s += As[g2][tid]; q += Bs[g2][tid]; }
            g_ps[(size_t)(bn+tid)*16 + blockIdx.y] = s;
            g_pq[(size_t)(bn+tid)*16 + blockIdx.y] = q;
        }
    } else {
        float* P = out + (size_t)blockIdx.z * M * N;
        #pragma unroll
        for (int i = 0; i < 8; i++) {
            float* o = P + (size_t)(bm+tm+i)*N + bn;
            #pragma unroll
            for (int j = 0; j < 8; j++) o[tn+j] = acc[i][j];
        }
    }
}

// ---------------- combine split-K partials + bias, fused latent BN stats (layout A, S=256) ----------------
// grid 256 x block 512: thread = channel, 8 rows per block.
__global__ void __launch_bounds__(512) combine_lat_stats(const float* __restrict__ bias)
{
    int c = threadIdx.x;
    int s = blockIdx.x;
    float bc = bias[c];
    float sum = 0.f, sq = 0.f;
    for (int r = s*8; r < s*8 + 8; r++) {
        size_t idx = (size_t)r*LAT + c;
        float v = g_gpart[idx] + g_gpart[(size_t)BB*LAT + idx]
                + g_gpart[2*(size_t)BB*LAT + idx] + g_gpart[3*(size_t)BB*LAT + idx] + bc;
        g_lat[idx] = v;
        sum += v; sq += v*v;
    }
    g_ps[(size_t)c*256 + s] = sum;
    g_pq[(size_t)c*256 + s] = sq;
}

// ---------------- fused latent activation + prototypes ----------------
__global__ void __launch_bounds__(512) latent_act_proto(float* __restrict__ xlat,
                                                        float* __restrict__ proto)
{
    int w = blockIdx.x;
    int c = threadIdx.x;
    float a = g_aL[c], bo = g_bL[c];
    float s = 0.f;
    #pragma unroll
    for (int j = 0; j < SHOT; j++) {
        size_t idx = (size_t)(w*SHOT + j)*LAT + c;
        float v = sigmoidf(a*g_lat[idx] + bo);
        xlat[idx] = v;
        s += v;
    }
    proto[w*LAT + c] = s * (1.f/SHOT);
}

__global__ void attn_radius_kernel(const float* __restrict__ proto, float* __restrict__ radius)
{
    int i = blockIdx.x;
    int tid = threadIdx.x;   // 64
    __shared__ float spi[LAT];
    __shared__ float att[WAYS];
    for (int l = tid; l < LAT; l += 64) spi[l] = proto[i*LAT + l];
    __syncthreads();
    float dot = 0.f;
    const float* pj = proto + tid*LAT;
    for (int l = 0; l < LAT; l++) dot += spi[l] * pj[l];
    att[tid] = dot;
    __syncthreads();
    float mx = -1e30f;
    for (int j = 0; j < WAYS; j++) mx = fmaxf(mx, att[j]);
    float ex = __expf(att[tid] - mx);
    __syncthreads();
    att[tid] = ex;
    __syncthreads();
    float sum = 0.f;
    for (int j = 0; j < WAYS; j++) sum += att[j];
    float inv = 1.f / sum;
    for (int r = 0; r < 8; r++) {
        int l = tid + (r << 6);
        float accv = 0.f;
        for (int j = 0; j < WAYS; j++) accv += att[j] * proto[j*LAT + l];
        radius[i*LAT + l] = spi[l] - accv * inv;
    }
}

// ---------------- deconv1: [B,128,7,7] -> [B,64,14,14], bnf fused, free stats ----------------
__global__ void __launch_bounds__(224) deconv1_kernel(const float* __restrict__ w,
                                                      const float* __restrict__ bias)
{
    int b = blockIdx.x;
    __shared__ float sin1[128*49];   // 25088 B
    const float* src = g_fc + (size_t)b * FLATD;
    int tid = threadIdx.x;
    for (int i = tid; i < FLATD; i += 224)
        sin1[i] = g_aF[i] * src[i] + g_bF[i];
    __syncthreads();
    int cg = tid / 14, oy = tid % 14;
    int co = 4*cg;
    float acc[4][14];
    #pragma unroll
    for (int u = 0; u < 4; u++) {
        float bb = bias[co+u];
        #pragma unroll
        for (int j = 0; j < 14; j++) acc[u][j] = bb;
    }
    int kyp = oy & 1;
    for (int ci = 0; ci < 128; ci++) {
        const float* inc = &sin1[ci*49];
        #pragma unroll
        for (int kyi = 0; kyi < 2; kyi++) {
            int ky = kyp + 2*kyi;
            int iy = (oy + ky - 2) >> 1;
            if ((unsigned)iy >= 7u) continue;
            float r[7];
            #pragma unroll
            for (int t = 0; t < 7; t++) r[t] = inc[iy*7 + t];
            float wr[4][4];
            #pragma unroll
            for (int u = 0; u < 4; u++) {
                float4 q = *reinterpret_cast<const float4*>(&w[(size_t)(ci*64 + co+u)*16 + (3-ky)*4]);
                wr[u][0] = q.w; wr[u][1] = q.z; wr[u][2] = q.y; wr[u][3] = q.x;
            }
            #pragma unroll
            for (int ox = 0; ox < 14; ox++) {
                int kxp = ox & 1;
                #pragma unroll
                for (int kxi = 0; kxi < 2; kxi++) {
                    int kx = kxp + 2*kxi;
                    int ix = (ox + kx - 2) >> 1;
                    if ((unsigned)ix < 7u) {
                        float rv = r[ix];
                        #pragma unroll
                        for (int u = 0; u < 4; u++)
                            acc[u][ox] += rv * wr[u][kx];
                    }
                }
            }
        }
    }
    #pragma unroll
    for (int u = 0; u < 4; u++) {
        float s = 0.f, q = 0.f;
        #pragma unroll
        for (int ox = 0; ox < 14; ox++) {
            float v = acc[u][ox];
            g_d1[(size_t)(b*64 + co+u)*196 + oy*14 + ox] = v;
            s += v; q += v*v;
        }
        g_ps[(size_t)b*896 + (co+u)*14 + oy] = s;   // layout B: stride=896, P=14
        g_pq[(size_t)b*896 + (co+u)*14 + oy] = q;
    }
}

// ---------------- deconv2: [B,64,14,14] -> [B,1,28,28], bnd1+leaky fused, fused stats ----------------
__global__ void __launch_bounds__(784) deconv2_kernel(const float* __restrict__ w,
                                                      const float* __restrict__ bias)
{
    int b = blockIdx.x;
    __shared__ float sin3[32*196];   // 25088 B
    __shared__ float swt[1024];
    __shared__ float rs[784], rq[784];
    int tid = threadIdx.x;
    for (int i = tid; i < 1024; i += 784) swt[i] = w[i];

    int oy = tid / 28, ox = tid % 28;
    int kyp = oy & 1, kxp = ox & 1;
    int iy0 = (oy + kyp - 2) >> 1;
    int iy1 = (oy + kyp) >> 1;
    int ix0 = (ox + kxp - 2) >> 1;
    int ix1 = (ox + kxp) >> 1;
    bool vy0 = (unsigned)iy0 < 14u, vy1 = (unsigned)iy1 < 14u;
    bool vx0 = (unsigned)ix0 < 14u, vx1 = (unsigned)ix1 < 14u;
    int o00 = (3-kyp)*4 + (3-kxp);
    int o01 = (3-kyp)*4 + (1-kxp);
    int o10 = (1-kyp)*4 + (3-kxp);
    int o11 = (1-kyp)*4 + (1-kxp);
    float acc = bias[0];

    for (int cc = 0; cc < 64; cc += 32) {
        __syncthreads();
        const float* src = g_d1 + ((size_t)b*64 + cc)*196;
        for (int i = tid; i < 32*196; i += 784) {
            int c = cc + i/196;
            sin3[i] = leakyf(g_aD1[c]*src[i] + g_bD1[c]);
        }
        __syncthreads();
        for (int ci = 0; ci < 32; ci++) {
            const float* sc = &sin3[ci*196];
            const float* wb = &swt[(cc+ci)*16];
            if (vy0 && vx0) acc += sc[iy0*14+ix0] * wb[o00];
            if (vy0 && vx1) acc += sc[iy0*14+ix1] * wb[o01];
            if (vy1 && vx0) acc += sc[iy1*14+ix0] * wb[o10];
            if (vy1 && vx1) acc += sc[iy1*14+ix1] * wb[o11];
        }
    }
    g_d2[(size_t)b*784 + tid] = acc;

    // fused single-channel stats: block reduction of 784 values (layout A, c=0, S=2048)
    rs[tid] = acc; rq[tid] = acc*acc;
    __syncthreads();
    if (tid < 272) { rs[tid] += rs[tid+512]; rq[tid] += rq[tid+512]; }
    __syncthreads();
    for (int st = 256; st > 0; st >>= 1) {
        if (tid < st) { rs[tid] += rs[tid+st]; rq[tid] += rq[tid+st]; }
        __syncthreads();
    }
    if (tid == 0) { g_ps[b] = rs[0]; g_pq[b] = rq[0]; }
}

__global__ void recon_out(float* __restrict__ out)
{
    int idx = blockIdx.x * blockDim.x + threadIdx.x;
    out[idx] = sigmoidf(g_aD2[0] * g_d2[idx] + g_bD2[0]);
}

// ---------------- host ----------------
extern "C" void kernel_launch(void* const* d_in, const int* in_sizes, int n_in,
                              void* d_out, int out_size)
{
    if (n_in < 26) return;
    const float* x      = (const float*)d_in[0];
    const float* gamma  = (const float*)d_in[1];
    const float* c1_w   = (const float*)d_in[2];
    const float* c1_b   = (const float*)d_in[3];
    const float* bn1_s  = (const float*)d_in[4];
    const float* bn1_b  = (const float*)d_in[5];
    const float* c2_w   = (const float*)d_in[6];
    const float* c2_b   = (const float*)d_in[7];
    const float* bn2_s  = (const float*)d_in[8];
    const float* bn2_b  = (const float*)d_in[9];
    const float* lat_w  = (const float*)d_in[10];
    const float* lat_b  = (const float*)d_in[11];
    const float* bnl_s  = (const float*)d_in[12];
    const float* bnl_b  = (const float*)d_in[13];
    const float* fc_w   = (const float*)d_in[14];
    const float* fc_b   = (const float*)d_in[15];
    const float* bnf_s  = (const float*)d_in[16];
    const float* bnf_b  = (const float*)d_in[17];
    const float* d1_w   = (const float*)d_in[18];
    const float* d1_b   = (const float*)d_in[19];
    const float* bnd1_s = (const float*)d_in[20];
    const float* bnd1_b = (const float*)d_in[21];
    const float* d2_w   = (const float*)d_in[22];
    const float* d2_b   = (const float*)d_in[23];
    const float* bnd2_s = (const float*)d_in[24];
    const float* bnd2_b = (const float*)d_in[25];

    float* out     = (float*)d_out;
    float* o_recon = out + OFF_RECON;
    float* o_proto = out + OFF_PROTO;
    float* o_rad   = out + OFF_RAD;
    float* o_lat   = out + OFF_LAT;

    void *p_h2, *p_gpart, *p_fc;
    cudaGetSymbolAddress(&p_h2,    g_h2);
    cudaGetSymbolAddress(&p_gpart, g_gpart);
    cudaGetSymbolAddress(&p_fc,    g_fc);

    void *p_a1, *p_b1, *p_a2, *p_b2, *p_aL, *p_bL, *p_aF, *p_bF, *p_aD1, *p_bD1, *p_aD2, *p_bD2;
    cudaGetSymbolAddress(&p_a1,  g_a1);   cudaGetSymbolAddress(&p_b1,  g_b1);
    cudaGetSymbolAddress(&p_a2,  g_a2);   cudaGetSymbolAddress(&p_b2,  g_b2);
    cudaGetSymbolAddress(&p_aL,  g_aL);   cudaGetSymbolAddress(&p_bL,  g_bL);
    cudaGetSymbolAddress(&p_aF,  g_aF);   cudaGetSymbolAddress(&p_bF,  g_bF);
    cudaGetSymbolAddress(&p_aD1, g_aD1);  cudaGetSymbolAddress(&p_bD1, g_bD1);
    cudaGetSymbolAddress(&p_aD2, g_aD2);  cudaGetSymbolAddress(&p_bD2, g_bD2);

    // ---- encoder ----
    conv1_kernel<<<BB, 256>>>(x, c1_w, c1_b);                       // + h1 stats (layout B)
    bn_finalize3<<<64, 512>>>(BB, 4, 256, 1.f/(BB*196.f), bn1_s, bn1_b, (float*)p_a1, (float*)p_b1);

    conv2_kernel<<<BB, 224>>>(c2_w, c2_b);                          // + h2 stats (layout B)
    bn_finalize3<<<128, 512>>>(BB, 7, 896, 1.f/(BB*49.f), bn2_s, bn2_b, (float*)p_a2, (float*)p_b2);

    // latent GEMM (split-K=4), bn2+leaky fused into A load
    sgemm_nt<1><<<dim3(LAT/128, BB/128, 4), 256>>>(
        (const float*)p_h2, lat_w, nullptr, (float*)p_gpart,
        BB, LAT, FLATD, FLATD/4, (const float*)p_a2, (const float*)p_b2,
        nullptr, nullptr);
    combine_lat_stats<<<256, 512>>>(lat_b);                         // + lat stats (layout A, S=256)
    bn_finalize2<<<LAT, 128>>>(256, 1.f/(float)BB, bnl_s, bnl_b, (float*)p_aL, (float*)p_bL);

    // ---- prototypes / radius (latent activation fused into proto pass) ----
    latent_act_proto<<<WAYS, LAT>>>(o_lat, o_proto);
    attn_radius_kernel<<<WAYS, 64>>>(o_proto, o_rad);

    // ---- decoder ----
    // fc GEMM; recon-latent shift (xlat + radius*gamma) fused into A load
    sgemm_nt<0><<<dim3(FLATD/128, BB/128, 1), 256>>>(               // + fc stats (layout A, S=16)
        o_lat, fc_w, fc_b, (float*)p_fc,
        BB, FLATD, LAT, LAT, nullptr, nullptr,
        o_rad, gamma);
    bn_finalize2<<<FLATD, 128>>>(16, 1.f/(float)BB, bnf_s, bnf_b, (float*)p_aF, (float*)p_bF);

    deconv1_kernel<<<BB, 224>>>(d1_w, d1_b);                        // + d1 stats (layout B)
    bn_finalize3<<<64, 512>>>(BB, 14, 896, 1.f/(BB*196.f), bnd1_s, bnd1_b, (float*)p_aD1, (float*)p_bD1);

    deconv2_kernel<<<BB, 784>>>(d2_w, d2_b);                        // + d2 stats (layout A, S=2048)
    bn_finalize2<<<1, 128>>>(2048, 1.f/(BB*784.f), bnd2_s, bnd2_b, (float*)p_aD2, (float*)p_bD2);

    recon_out<<<BB*784/256, 256>>>(o_recon);
}

// round 16
// speedup vs baseline: 1.0413x; 1.0065x over previous
#include <cuda_runtime.h>

// ---------------- problem constants ----------------
#define BB     2048
#define WAYS   64
#define SHOT   32
#define LAT    512
#define FLATD  6272
#define EPSBN  1e-5f
#define SLOPE  0.2f

#define OFF_RECON 0
#define OFF_PROTO 1605632
#define OFF_RAD   1638400
#define OFF_LAT   1671168

// ---------------- scratch (device globals; no runtime alloc) ----------------
__device__ float g_h1 [BB*64*196];   // conv1 raw
__device__ float g_h2 [BB*128*49];   // conv2 raw
__device__ float g_lat[BB*LAT];      // latent pre-BN
__device__ float g_fc [BB*FLATD];    // fc raw
__device__ float g_d1 [BB*64*196];   // deconv1 raw
__device__ float g_d2 [BB*784];      // deconv2 raw
__device__ float g_gpart[4*BB*LAT];  // split-K partials

__device__ float g_ps[1835008];      // BN partial sums
__device__ float g_pq[1835008];      // BN partial sumsq

__device__ float g_a1[64],  g_b1[64];
__device__ float g_a2[128], g_b2[128];
__device__ float g_aL[LAT], g_bL[LAT];
__device__ float g_aF[FLATD], g_bF[FLATD];
__device__ float g_aD1[64], g_bD1[64];
__device__ float g_aD2[1],  g_bD2[1];

__device__ __forceinline__ float leakyf(float v){ return v >= 0.f ? v : SLOPE*v; }
__device__ __forceinline__ float sigmoidf(float v){ return 1.f/(1.f+__expf(-v)); }

// ---------------- BN finalize, layout A: g_ps[c*S + i] ----------------
__global__ void bn_finalize2(int S, float invN,
                             const float* __restrict__ scale, const float* __restrict__ bias,
                             float* __restrict__ ga, float* __restrict__ gb)
{
    int c = blockIdx.x;
    __shared__ float rs[128], rq[128];
    float s = 0.f, q = 0.f;
    for (int i = threadIdx.x; i < S; i += 128) {
        s += g_ps[(size_t)c*S + i];
        q += g_pq[(size_t)c*S + i];
    }
    rs[threadIdx.x] = s; rq[threadIdx.x] = q;
    __syncthreads();
    for (int st = 64; st > 0; st >>= 1) {
        if (threadIdx.x < st) { rs[threadIdx.x] += rs[threadIdx.x+st]; rq[threadIdx.x] += rq[threadIdx.x+st]; }
        __syncthreads();
    }
    if (threadIdx.x == 0) {
        float m = rs[0] * invN;
        float v = rq[0] * invN - m * m;
        float inv = rsqrtf(v + EPSBN);
        float a = scale[c] * inv;
        ga[c] = a;
        gb[c] = bias[c] - m * a;
    }
}

// ---------------- BN finalize, layout B: g_ps[b*stride + c*P + p] — 512 threads ----------------
__global__ void __launch_bounds__(512) bn_finalize3(int nb, int P, int stride, float invN,
                             const float* __restrict__ scale, const float* __restrict__ bias,
                             float* __restrict__ ga, float* __restrict__ gb)
{
    int c = blockIdx.x;
    __shared__ float rs[512], rq[512];
    float s = 0.f, q = 0.f;
    int n = nb * P;
    for (int i = threadIdx.x; i < n; i += 512) {
        int b = i / P, p = i % P;
        size_t idx = (size_t)b*stride + c*P + p;
        s += g_ps[idx];
        q += g_pq[idx];
    }
    rs[threadIdx.x] = s; rq[threadIdx.x] = q;
    __syncthreads();
    for (int st = 256; st > 0; st >>= 1) {
        if (threadIdx.x < st) { rs[threadIdx.x] += rs[threadIdx.x+st]; rq[threadIdx.x] += rq[threadIdx.x+st]; }
        __syncthreads();
    }
    if (threadIdx.x == 0) {
        float m = rs[0] * invN;
        float v = rq[0] * invN - m * m;
        float inv = rsqrtf(v + EPSBN);
        float a = scale[c] * inv;
        ga[c] = a;
        gb[c] = bias[c] - m * a;
    }
}

// ---------------- conv1: [B,1,28,28] -> [B,64,14,14], register-stationary + free stats ----------------
__global__ void __launch_bounds__(256) conv1_kernel(const float* __restrict__ x,
                             const float* __restrict__ w, const float* __restrict__ bias)
{
    int b = blockIdx.x;
    __shared__ float sx[784];
    __shared__ float sw[1024];
    int tid = threadIdx.x;
    for (int i = tid; i < 784;  i += 256) sx[i] = x[b*784 + i];
    for (int i = tid; i < 1024; i += 256) sw[i] = w[i];
    __syncthreads();

    int c = tid >> 2, qd = tid & 3;
    float bb = bias[c];
    const float* wc = &sw[c*16];
    float* dst = &g_h1[(size_t)(b*64 + c)*196];
    float s = 0.f, q = 0.f;
    #pragma unroll 7
    for (int t = 0; t < 49; t++) {
        int pix = qd*49 + t;
        int oy = pix / 14, ox = pix % 14;
        float acc = bb;
        #pragma unroll
        for (int ky = 0; ky < 4; ky++) {
            int iy = 2*oy + ky - 1;
            if ((unsigned)iy < 28u) {
                #pragma unroll
                for (int kx = 0; kx < 4; kx++) {
                    int ix = 2*ox + kx - 1;
                    if ((unsigned)ix < 28u)
                        acc += sx[iy*28+ix] * wc[ky*4+kx];
                }
            }
        }
        dst[pix] = acc;
        s += acc; q += acc*acc;
    }
    g_ps[(size_t)b*256 + tid] = s;   // layout B: stride=256, P=4
    g_pq[(size_t)b*256 + tid] = q;
}

// ---------------- conv2: [B,64,14,14] -> [B,128,7,7], bn1+leaky fused, free stats ----------------
__global__ void __launch_bounds__(224) conv2_kernel(const float* __restrict__ w,
                                                    const float* __restrict__ bias)
{
    int b = blockIdx.x;
    __shared__ float sin2[32*196];   // 25088 B
    int tid = threadIdx.x;
    int cg = tid / 7, oy = tid % 7;
    int co = 4*cg;
    float acc[4][7];
    #pragma unroll
    for (int u = 0; u < 4; u++) {
        float bb = bias[co+u];
        #pragma unroll
        for (int j = 0; j < 7; j++) acc[u][j] = bb;
    }

    for (int cc = 0; cc < 64; cc += 32) {
        __syncthreads();   // previous chunk fully consumed
        const float* src = g_h1 + ((size_t)b*64 + cc)*196;
        for (int i = tid; i < 32*196; i += 224) {
            int c = cc + i/196;
            sin2[i] = leakyf(g_a1[c]*src[i] + g_b1[c]);
        }
        __syncthreads();
        for (int ci = 0; ci < 32; ci++) {
            const float* inc = &sin2[ci*196];
            int cig = cc + ci;
            #pragma unroll
            for (int ky = 0; ky < 4; ky++) {
                int iy = 2*oy + ky - 1;
                if ((unsigned)iy >= 14u) continue;
                float rE[16];
                rE[0] = 0.f; rE[15] = 0.f;
                #pragma unroll
                for (int t = 0; t < 14; t++) rE[t+1] = inc[iy*14 + t];
                float4 wv[4];
                #pragma unroll
                for (int u = 0; u < 4; u++)
                    wv[u] = *reinterpret_cast<const float4*>(&w[(size_t)((co+u)*64 + cig)*16 + ky*4]);
                #pragma unroll
                for (int ox = 0; ox < 7; ox++) {
                    int p = 2*ox;
                    float e0 = rE[p], e1 = rE[p+1], e2 = rE[p+2], e3 = rE[p+3];
                    #pragma unroll
                    for (int u = 0; u < 4; u++)
                        acc[u][ox] += e0*wv[u].x + e1*wv[u].y + e2*wv[u].z + e3*wv[u].w;
                }
            }
        }
    }
    #pragma unroll
    for (int u = 0; u < 4; u++) {
        float s = 0.f, q = 0.f;
        #pragma unroll
        for (int ox = 0; ox < 7; ox++) {
            float v = acc[u][ox];
            g_h2[(size_t)(b*128 + co+u)*49 + oy*7 + ox] = v;
            s += v; q += v*v;
        }
        g_ps[(size_t)b*896 + (co+u)*7 + oy] = s;   // layout B: stride=896, P=7
        g_pq[(size_t)b*896 + (co+u)*7 + oy] = q;
    }
}

// ---------------- SGEMM NT, KB=32: C[M,N] = act(A)[M,K] * W[N,K]^T (+bias) ----------------
// MODE 1: latent GEMM, A gets bn2-affine + leaky (c=k/49), split-K partial output.
// MODE 0: fc GEMM; A = xlat + radius*gamma fused on load; bias + fused BN stats (layout A, S=16).
template<int MODE>
__global__ void __launch_bounds__(256) sgemm_nt(
    const float* __restrict__ A, const float* __restrict__ W,
    const float* __restrict__ bias, float* __restrict__ out,
    int M, int N, int K, int Ktile,
    const float* __restrict__ ca, const float* __restrict__ cb,
    const float* __restrict__ radius, const float* __restrict__ gamma)
{
    __shared__ float As[32][128];
    __shared__ float Bs[32][128];
    const int tid = threadIdx.x;
    const int bm = blockIdx.y * 128;
    const int bn = blockIdx.x * 128;
    const int lr = tid >> 2;          // 0..63
    const int lc = (tid & 3) << 3;    // 0,8,16,24
    const int tm = (tid >> 4) << 3;
    const int tn = (tid & 15) << 3;
    float acc[8][8];
    #pragma unroll
    for (int i = 0; i < 8; i++)
        #pragma unroll
        for (int j = 0; j < 8; j++) acc[i][j] = 0.f;

    float gm = (MODE == 0) ? gamma[0] : 0.f;

    const int k0beg = blockIdx.z * Ktile;
    for (int k0 = k0beg; k0 < k0beg + Ktile; k0 += 32) {
        #pragma unroll
        for (int h = 0; h < 2; h++) {
            int row = bm + lr + (h << 6);
            const float* ap = A + (size_t)row*K + k0 + lc;
            float4 v0 = *reinterpret_cast<const float4*>(ap);
            float4 v1 = *reinterpret_cast<const float4*>(ap + 4);
            if (MODE == 1) {
                int kb = k0 + lc;
                int c0=(kb  )/49, c1=(kb+1)/49, c2=(kb+2)/49, c3=(kb+3)/49;
                int c4=(kb+4)/49, c5=(kb+5)/49, c6=(kb+6)/49, c7=(kb+7)/49;
                v0.x = leakyf(ca[c0]*v0.x + cb[c0]);
                v0.y = leakyf(ca[c1]*v0.y + cb[c1]);
                v0.z = leakyf(ca[c2]*v0.z + cb[c2]);
                v0.w = leakyf(ca[c3]*v0.w + cb[c3]);
                v1.x = leakyf(ca[c4]*v1.x + cb[c4]);
                v1.y = leakyf(ca[c5]*v1.y + cb[c5]);
                v1.z = leakyf(ca[c6]*v1.z + cb[c6]);
                v1.w = leakyf(ca[c7]*v1.w + cb[c7]);
            } else {
                int wdx = row >> 5;   // class index (row / SHOT)
                const float* rp = radius + (wdx << 9) + k0 + lc;
                float4 r0 = *reinterpret_cast<const float4*>(rp);
                float4 r1 = *reinterpret_cast<const float4*>(rp + 4);
                v0.x += r0.x * gm; v0.y += r0.y * gm; v0.z += r0.z * gm; v0.w += r0.w * gm;
                v1.x += r1.x * gm; v1.y += r1.y * gm; v1.z += r1.z * gm; v1.w += r1.w * gm;
            }
            int wrow = bn + lr + (h << 6);
            const float* wp = W + (size_t)wrow*K + k0 + lc;
            float4 w0 = *reinterpret_cast<const float4*>(wp);
            float4 w1 = *reinterpret_cast<const float4*>(wp + 4);

            int r = lr + (h << 6);
            As[lc+0][r] = v0.x; As[lc+1][r] = v0.y; As[lc+2][r] = v0.z; As[lc+3][r] = v0.w;
            As[lc+4][r] = v1.x; As[lc+5][r] = v1.y; As[lc+6][r] = v1.z; As[lc+7][r] = v1.w;
            Bs[lc+0][r] = w0.x; Bs[lc+1][r] = w0.y; Bs[lc+2][r] = w0.z; Bs[lc+3][r] = w0.w;
            Bs[lc+4][r] = w1.x; Bs[lc+5][r] = w1.y; Bs[lc+6][r] = w1.z; Bs[lc+7][r] = w1.w;
        }
        __syncthreads();
        #pragma unroll
        for (int kk = 0; kk < 32; kk++) {
            float a[8], bb[8];
            #pragma unroll
            for (int i = 0; i < 8; i++) a[i]  = As[kk][tm+i];
            #pragma unroll
            for (int j = 0; j < 8; j++) bb[j] = Bs[kk][tn+j];
            #pragma unroll
            for (int i = 0; i < 8; i++)
                #pragma unroll
                for (int j = 0; j < 8; j++) acc[i][j] += a[i]*bb[j];
        }
        __syncthreads();
    }

    if (MODE == 0) {
        float cs[8], cq[8];
        #pragma unroll
        for (int j = 0; j < 8; j++) { cs[j] = 0.f; cq[j] = 0.f; }
        #pragma unroll
        for (int i = 0; i < 8; i++) {
            float* o = out + (size_t)(bm+tm+i)*N + bn;
            #pragma unroll
            for (int j = 0; j < 8; j++) {
                float v = acc[i][j] + bias[bn+tn+j];
                o[tn+j] = v;
                cs[j] += v; cq[j] += v*v;
            }
        }
        // reduce per-column partials through As/Bs (free after last loop sync)
        int g = tid >> 4;
        #pragma unroll
        for (int j = 0; j < 8; j++) { As[g][tn+j] = cs[j]; Bs[g][tn+j] = cq[j]; }
        __syncthreads();
        if (tid < 128) {
            float s = 0.f, q = 0.f;
            #pragma unroll
            for (int g2 = 0; g2 < 16; g2++) { s += As[g2][tid]; q += Bs[g2][tid]; }
            g_ps[(size_t)(bn+tid)*16 + blockIdx.y] = s;
            g_pq[(size_t)(bn+tid)*16 + blockIdx.y] = q;
        }
    } else {
        float* P = out + (size_t)blockIdx.z * M * N;
        #pragma unroll
        for (int i = 0; i < 8; i++) {
            float* o = P + (size_t)(bm+tm+i)*N + bn;
            #pragma unroll
            for (int j = 0; j < 8; j++) o[tn+j] = acc[i][j];
        }
    }
}

// ---------------- combine split-K partials + bias, fused latent BN stats (layout A, S=256) ----------------
__global__ void __launch_bounds__(512) combine_lat_stats(const float* __restrict__ bias)
{
    int c = threadIdx.x;
    int s = blockIdx.x;
    float bc = bias[c];
    float sum = 0.f, sq = 0.f;
    for (int r = s*8; r < s*8 + 8; r++) {
        size_t idx = (size_t)r*LAT + c;
        float v = g_gpart[idx] + g_gpart[(size_t)BB*LAT + idx]
                + g_gpart[2*(size_t)BB*LAT + idx] + g_gpart[3*(size_t)BB*LAT + idx] + bc;
        g_lat[idx] = v;
        sum += v; sq += v*v;
    }
    g_ps[(size_t)c*256 + s] = sum;
    g_pq[(size_t)c*256 + s] = sq;
}

// ---------------- fused latent activation + prototypes ----------------
__global__ void __launch_bounds__(512) latent_act_proto(float* __restrict__ xlat,
                                                        float* __restrict__ proto)
{
    int w = blockIdx.x;
    int c = threadIdx.x;
    float a = g_aL[c], bo = g_bL[c];
    float s = 0.f;
    #pragma unroll
    for (int j = 0; j < SHOT; j++) {
        size_t idx = (size_t)(w*SHOT + j)*LAT + c;
        float v = sigmoidf(a*g_lat[idx] + bo);
        xlat[idx] = v;
        s += v;
    }
    proto[w*LAT + c] = s * (1.f/SHOT);
}

__global__ void attn_radius_kernel(const float* __restrict__ proto, float* __restrict__ radius)
{
    int i = blockIdx.x;
    int tid = threadIdx.x;   // 64
    __shared__ float spi[LAT];
    __shared__ float att[WAYS];
    for (int l = tid; l < LAT; l += 64) spi[l] = proto[i*LAT + l];
    __syncthreads();
    float dot = 0.f;
    const float* pj = proto + tid*LAT;
    for (int l = 0; l < LAT; l++) dot += spi[l] * pj[l];
    att[tid] = dot;
    __syncthreads();
    float mx = -1e30f;
    for (int j = 0; j < WAYS; j++) mx = fmaxf(mx, att[j]);
    float ex = __expf(att[tid] - mx);
    __syncthreads();
    att[tid] = ex;
    __syncthreads();
    float sum = 0.f;
    for (int j = 0; j < WAYS; j++) sum += att[j];
    float inv = 1.f / sum;
    for (int r = 0; r < 8; r++) {
        int l = tid + (r << 6);
        float accv = 0.f;
        for (int j = 0; j < WAYS; j++) accv += att[j] * proto[j*LAT + l];
        radius[i*LAT + l] = spi[l] - accv * inv;
    }
}

// ---------------- deconv1: [B,128,7,7] -> [B,64,14,14], bnf fused, free stats ----------------
__global__ void __launch_bounds__(224) deconv1_kernel(const float* __restrict__ w,
                                                      const float* __restrict__ bias)
{
    int b = blockIdx.x;
    __shared__ float sin1[128*49];   // 25088 B
    const float* src = g_fc + (size_t)b * FLATD;
    int tid = threadIdx.x;
    for (int i = tid; i < FLATD; i += 224)
        sin1[i] = g_aF[i] * src[i] + g_bF[i];
    __syncthreads();
    int cg = tid / 14, oy = tid % 14;
    int co = 4*cg;
    float acc[4][14];
    #pragma unroll
    for (int u = 0; u < 4; u++) {
        float bb = bias[co+u];
        #pragma unroll
        for (int j = 0; j < 14; j++) acc[u][j] = bb;
    }
    int kyp = oy & 1;
    for (int ci = 0; ci < 128; ci++) {
        const float* inc = &sin1[ci*49];
        #pragma unroll
        for (int kyi = 0; kyi < 2; kyi++) {
            int ky = kyp + 2*kyi;
            int iy = (oy + ky - 2) >> 1;
            if ((unsigned)iy >= 7u) continue;
            float r[7];
            #pragma unroll
            for (int t = 0; t < 7; t++) r[t] = inc[iy*7 + t];
            float wr[4][4];
            #pragma unroll
            for (int u = 0; u < 4; u++) {
                float4 q = *reinterpret_cast<const float4*>(&w[(size_t)(ci*64 + co+u)*16 + (3-ky)*4]);
                wr[u][0] = q.w; wr[u][1] = q.z; wr[u][2] = q.y; wr[u][3] = q.x;
            }
            #pragma unroll
            for (int ox = 0; ox < 14; ox++) {
                int kxp = ox & 1;
                #pragma unroll
                for (int kxi = 0; kxi < 2; kxi++) {
                    int kx = kxp + 2*kxi;
                    int ix = (ox + kx - 2) >> 1;
                    if ((unsigned)ix < 7u) {
                        float rv = r[ix];
                        #pragma unroll
                        for (int u = 0; u < 4; u++)
                            acc[u][ox] += rv * wr[u][kx];
                    }
                }
            }
        }
    }
    #pragma unroll
    for (int u = 0; u < 4; u++) {
        float s = 0.f, q = 0.f;
        #pragma unroll
        for (int ox = 0; ox < 14; ox++) {
            float v = acc[u][ox];
            g_d1[(size_t)(b*64 + co+u)*196 + oy*14 + ox] = v;
            s += v; q += v*v;
        }
        g_ps[(size_t)b*896 + (co+u)*14 + oy] = s;   // layout B: stride=896, P=14
        g_pq[(size_t)b*896 + (co+u)*14 + oy] = q;
    }
}

// ---------------- deconv2: [B,64,14,14] -> [B,1,28,28], bnd1+leaky fused, fused stats ----------------
__global__ void __launch_bounds__(784) deconv2_kernel(const float* __restrict__ w,
                                                      const float* __restrict__ bias)
{
    int b = blockIdx.x;
    __shared__ float sin3[32*196];   // 25088 B
    __shared__ float swt[1024];
    __shared__ float rs[784], rq[784];
    int tid = threadIdx.x;
    for (int i = tid; i < 1024; i += 784) swt[i] = w[i];

    int oy = tid / 28, ox = tid % 28;
    int kyp = oy & 1, kxp = ox & 1;
    int iy0 = (oy + kyp - 2) >> 1;
    int iy1 = (oy + kyp) >> 1;
    int ix0 = (ox + kxp - 2) >> 1;
    int ix1 = (ox + kxp) >> 1;
    bool vy0 = (unsigned)iy0 < 14u, vy1 = (unsigned)iy1 < 14u;
    bool vx0 = (unsigned)ix0 < 14u, vx1 = (unsigned)ix1 < 14u;
    int o00 = (3-kyp)*4 + (3-kxp);
    int o01 = (3-kyp)*4 + (1-kxp);
    int o10 = (1-kyp)*4 + (3-kxp);
    int o11 = (1-kyp)*4 + (1-kxp);
    float acc = bias[0];

    for (int cc = 0; cc < 64; cc += 32) {
        __syncthreads();
        const float* src = g_d1 + ((size_t)b*64 + cc)*196;
        for (int i = tid; i < 32*196; i += 784) {
            int c = cc + i/196;
            sin3[i] = leakyf(g_aD1[c]*src[i] + g_bD1[c]);
        }
        __syncthreads();
        for (int ci = 0; ci < 32; ci++) {
            const float* sc = &sin3[ci*196];
            const float* wb = &swt[(cc+ci)*16];
            if (vy0 && vx0) acc += sc[iy0*14+ix0] * wb[o00];
            if (vy0 && vx1) acc += sc[iy0*14+ix1] * wb[o01];
            if (vy1 && vx0) acc += sc[iy1*14+ix0] * wb[o10];
            if (vy1 && vx1) acc += sc[iy1*14+ix1] * wb[o11];
        }
    }
    g_d2[(size_t)b*784 + tid] = acc;

    // fused single-channel stats: block reduction of 784 values (layout A, c=0, S=2048)
    rs[tid] = acc; rq[tid] = acc*acc;
    __syncthreads();
    if (tid < 272) { rs[tid] += rs[tid+512]; rq[tid] += rq[tid+512]; }
    __syncthreads();
    for (int st = 256; st > 0; st >>= 1) {
        if (tid < st) { rs[tid] += rs[tid+st]; rq[tid] += rq[tid+st]; }
        __syncthreads();
    }
    if (tid == 0) { g_ps[b] = rs[0]; g_pq[b] = rq[0]; }
}

__global__ void recon_out(float* __restrict__ out)
{
    int idx = blockIdx.x * blockDim.x + threadIdx.x;
    out[idx] = sigmoidf(g_aD2[0] * g_d2[idx] + g_bD2[0]);
}

// ---------------- host ----------------
extern "C" void kernel_launch(void* const* d_in, const int* in_sizes, int n_in,
                              void* d_out, int out_size)
{
    if (n_in < 26) return;
    const float* x      = (const float*)d_in[0];
    const float* gamma  = (const float*)d_in[1];
    const float* c1_w   = (const float*)d_in[2];
    const float* c1_b   = (const float*)d_in[3];
    const float* bn1_s  = (const float*)d_in[4];
    const float* bn1_b  = (const float*)d_in[5];
    const float* c2_w   = (const float*)d_in[6];
    const float* c2_b   = (const float*)d_in[7];
    const float* bn2_s  = (const float*)d_in[8];
    const float* bn2_b  = (const float*)d_in[9];
    const float* lat_w  = (const float*)d_in[10];
    const float* lat_b  = (const float*)d_in[11];
    const float* bnl_s  = (const float*)d_in[12];
    const float* bnl_b  = (const float*)d_in[13];
    const float* fc_w   = (const float*)d_in[14];
    const float* fc_b   = (const float*)d_in[15];
    const float* bnf_s  = (const float*)d_in[16];
    const float* bnf_b  = (const float*)d_in[17];
    const float* d1_w   = (const float*)d_in[18];
    const float* d1_b   = (const float*)d_in[19];
    const float* bnd1_s = (const float*)d_in[20];
    const float* bnd1_b = (const float*)d_in[21];
    const float* d2_w   = (const float*)d_in[22];
    const float* d2_b   = (const float*)d_in[23];
    const float* bnd2_s = (const float*)d_in[24];
    const float* bnd2_b = (const float*)d_in[25];

    float* out     = (float*)d_out;
    float* o_recon = out + OFF_RECON;
    float* o_proto = out + OFF_PROTO;
    float* o_rad   = out + OFF_RAD;
    float* o_lat   = out + OFF_LAT;

    void *p_h2, *p_gpart, *p_fc;
    cudaGetSymbolAddress(&p_h2,    g_h2);
    cudaGetSymbolAddress(&p_gpart, g_gpart);
    cudaGetSymbolAddress(&p_fc,    g_fc);

    void *p_a1, *p_b1, *p_a2, *p_b2, *p_aL, *p_bL, *p_aF, *p_bF, *p_aD1, *p_bD1, *p_aD2, *p_bD2;
    cudaGetSymbolAddress(&p_a1,  g_a1);   cudaGetSymbolAddress(&p_b1,  g_b1);
    cudaGetSymbolAddress(&p_a2,  g_a2);   cudaGetSymbolAddress(&p_b2,  g_b2);
    cudaGetSymbolAddress(&p_aL,  g_aL);   cudaGetSymbolAddress(&p_bL,  g_bL);
    cudaGetSymbolAddress(&p_aF,  g_aF);   cudaGetSymbolAddress(&p_bF,  g_bF);
    cudaGetSymbolAddress(&p_aD1, g_aD1);  cudaGetSymbolAddress(&p_bD1, g_bD1);
    cudaGetSymbolAddress(&p_aD2, g_aD2);  cudaGetSymbolAddress(&p_bD2, g_bD2);

    // ---- encoder ----
    conv1_kernel<<<BB, 256>>>(x, c1_w, c1_b);                       // + h1 stats (layout B)
    bn_finalize3<<<64, 512>>>(BB, 4, 256, 1.f/(BB*196.f), bn1_s, bn1_b, (float*)p_a1, (float*)p_b1);

    conv2_kernel<<<BB, 224>>>(c2_w, c2_b);                          // + h2 stats (layout B)
    bn_finalize3<<<128, 512>>>(BB, 7, 896, 1.f/(BB*49.f), bn2_s, bn2_b, (float*)p_a2, (float*)p_b2);

    // latent GEMM (split-K=4, KB=32), bn2+leaky fused into A load
    sgemm_nt<1><<<dim3(LAT/128, BB/128, 4), 256>>>(
        (const float*)p_h2, lat_w, nullptr, (float*)p_gpart,
        BB, LAT, FLATD, FLATD/4, (const float*)p_a2, (const float*)p_b2,
        nullptr, nullptr);
    combine_lat_stats<<<256, 512>>>(lat_b);                         // + lat stats (layout A, S=256)
    bn_finalize2<<<LAT, 128>>>(256, 1.f/(float)BB, bnl_s, bnl_b, (float*)p_aL, (float*)p_bL);

    // ---- prototypes / radius (latent activation fused into proto pass) ----
    latent_act_proto<<<WAYS, LAT>>>(o_lat, o_proto);
    attn_radius_kernel<<<WAYS, 64>>>(o_proto, o_rad);

    // ---- decoder ----
    // fc GEMM (KB=32); recon-latent shift (xlat + radius*gamma) fused into A load
    sgemm_nt<0><<<dim3(FLATD/128, BB/128, 1), 256>>>(               // + fc stats (layout A, S=16)
        o_lat, fc_w, fc_b, (float*)p_fc,
        BB, FLATD, LAT, LAT, nullptr, nullptr,
        o_rad, gamma);
    bn_finalize2<<<FLATD, 128>>>(16, 1.f/(float)BB, bnf_s, bnf_b, (float*)p_aF, (float*)p_bF);

    deconv1_kernel<<<BB, 224>>>(d1_w, d1_b);                        // + d1 stats (layout B)
    bn_finalize3<<<64, 512>>>(BB, 14, 896, 1.f/(BB*196.f), bnd1_s, bnd1_b, (float*)p_aD1, (float*)p_bD1);

    deconv2_kernel<<<BB, 784>>>(d2_w, d2_b);                        // + d2 stats (layout A, S=2048)
    bn_finalize2<<<1, 128>>>(2048, 1.f/(BB*784.f), bnd2_s, bnd2_b, (float*)p_aD2, (float*)p_bD2);

    recon_out<<<BB*784/256, 256>>>(o_recon);
}

// round 17
// speedup vs baseline: 1.0475x; 1.0059x over previous
#include <cuda_runtime.h>

// ---------------- problem constants ----------------
#define BB     2048
#define WAYS   64
#define SHOT   32
#define LAT    512
#define FLATD  6272
#define EPSBN  1e-5f
#define SLOPE  0.2f

#define OFF_RECON 0
#define OFF_PROTO 1605632
#define OFF_RAD   1638400
#define OFF_LAT   1671168

// ---------------- scratch (device globals; no runtime alloc) ----------------
__device__ float g_h1 [BB*64*196];   // conv1 raw
__device__ float g_h2 [BB*128*49];   // conv2 raw
__device__ float g_lat[BB*LAT];      // latent pre-BN
__device__ float g_fc [BB*FLATD];    // fc raw
__device__ float g_d1 [BB*64*196];   // deconv1 raw
__device__ float g_d2 [BB*784];      // deconv2 raw
__device__ float g_gpart[4*BB*LAT];  // split-K partials

__device__ float g_ps[1835008];      // BN partial sums
__device__ float g_pq[1835008];      // BN partial sumsq

__device__ float g_a1[64],  g_b1[64];
__device__ float g_a2[128], g_b2[128];
__device__ float g_aL[LAT], g_bL[LAT];
__device__ float g_aF[FLATD], g_bF[FLATD];
__device__ float g_aD1[64], g_bD1[64];
__device__ float g_aD2[1],  g_bD2[1];

__device__ __forceinline__ float leakyf(float v){ return v >= 0.f ? v : SLOPE*v; }
__device__ __forceinline__ float sigmoidf(float v){ return 1.f/(1.f+__expf(-v)); }

// ---------------- BN finalize, layout A: g_ps[c*S + i] ----------------
__global__ void bn_finalize2(int S, float invN,
                             const float* __restrict__ scale, const float* __restrict__ bias,
                             float* __restrict__ ga, float* __restrict__ gb)
{
    int c = blockIdx.x;
    __shared__ float rs[128], rq[128];
    float s = 0.f, q = 0.f;
    for (int i = threadIdx.x; i < S; i += 128) {
        s += g_ps[(size_t)c*S + i];
        q += g_pq[(size_t)c*S + i];
    }
    rs[threadIdx.x] = s; rq[threadIdx.x] = q;
    __syncthreads();
    for (int st = 64; st > 0; st >>= 1) {
        if (threadIdx.x < st) { rs[threadIdx.x] += rs[threadIdx.x+st]; rq[threadIdx.x] += rq[threadIdx.x+st]; }
        __syncthreads();
    }
    if (threadIdx.x == 0) {
        float m = rs[0] * invN;
        float v = rq[0] * invN - m * m;
        float inv = rsqrtf(v + EPSBN);
        float a = scale[c] * inv;
        ga[c] = a;
        gb[c] = bias[c] - m * a;
    }
}

// ---------------- BN finalize, layout B: g_ps[b*stride + c*P + p] — 512 threads ----------------
__global__ void __launch_bounds__(512) bn_finalize3(int nb, int P, int stride, float invN,
                             const float* __restrict__ scale, const float* __restrict__ bias,
                             float* __restrict__ ga, float* __restrict__ gb)
{
    int c = blockIdx.x;
    __shared__ float rs[512], rq[512];
    float s = 0.f, q = 0.f;
    int n = nb * P;
    for (int i = threadIdx.x; i < n; i += 512) {
        int b = i / P, p = i % P;
        size_t idx = (size_t)b*stride + c*P + p;
        s += g_ps[idx];
        q += g_pq[idx];
    }
    rs[threadIdx.x] = s; rq[threadIdx.x] = q;
    __syncthreads();
    for (int st = 256; st > 0; st >>= 1) {
        if (threadIdx.x < st) { rs[threadIdx.x] += rs[threadIdx.x+st]; rq[threadIdx.x] += rq[threadIdx.x+st]; }
        __syncthreads();
    }
    if (threadIdx.x == 0) {
        float m = rs[0] * invN;
        float v = rq[0] * invN - m * m;
        float inv = rsqrtf(v + EPSBN);
        float a = scale[c] * inv;
        ga[c] = a;
        gb[c] = bias[c] - m * a;
    }
}

// ---------------- conv1: [B,1,28,28] -> [B,64,14,14], register-stationary + free stats ----------------
__global__ void __launch_bounds__(256) conv1_kernel(const float* __restrict__ x,
                             const float* __restrict__ w, const float* __restrict__ bias)
{
    int b = blockIdx.x;
    __shared__ float sx[784];
    __shared__ float sw[1024];
    int tid = threadIdx.x;
    for (int i = tid; i < 784;  i += 256) sx[i] = x[b*784 + i];
    for (int i = tid; i < 1024; i += 256) sw[i] = w[i];
    __syncthreads();

    int c = tid >> 2, qd = tid & 3;
    float bb = bias[c];
    const float* wc = &sw[c*16];
    float* dst = &g_h1[(size_t)(b*64 + c)*196];
    float s = 0.f, q = 0.f;
    #pragma unroll 7
    for (int t = 0; t < 49; t++) {
        int pix = qd*49 + t;
        int oy = pix / 14, ox = pix % 14;
        float acc = bb;
        #pragma unroll
        for (int ky = 0; ky < 4; ky++) {
            int iy = 2*oy + ky - 1;
            if ((unsigned)iy < 28u) {
                #pragma unroll
                for (int kx = 0; kx < 4; kx++) {
                    int ix = 2*ox + kx - 1;
                    if ((unsigned)ix < 28u)
                        acc += sx[iy*28+ix] * wc[ky*4+kx];
                }
            }
        }
        dst[pix] = acc;
        s += acc; q += acc*acc;
    }
    g_ps[(size_t)b*256 + tid] = s;   // layout B: stride=256, P=4
    g_pq[(size_t)b*256 + tid] = q;
}

// ---------------- conv2: [B,64,14,14] -> [B,128,7,7], bn1+leaky fused, free stats ----------------
__global__ void __launch_bounds__(224) conv2_kernel(const float* __restrict__ w,
                                                    const float* __restrict__ bias)
{
    int b = blockIdx.x;
    __shared__ float sin2[32*196];   // 25088 B
    int tid = threadIdx.x;
    int cg = tid / 7, oy = tid % 7;
    int co = 4*cg;
    float acc[4][7];
    #pragma unroll
    for (int u = 0; u < 4; u++) {
        float bb = bias[co+u];
        #pragma unroll
        for (int j = 0; j < 7; j++) acc[u][j] = bb;
    }

    for (int cc = 0; cc < 64; cc += 32) {
        __syncthreads();   // previous chunk fully consumed
        const float* src = g_h1 + ((size_t)b*64 + cc)*196;
        for (int i = tid; i < 32*196; i += 224) {
            int c = cc + i/196;
            sin2[i] = leakyf(g_a1[c]*src[i] + g_b1[c]);
        }
        __syncthreads();
        for (int ci = 0; ci < 32; ci++) {
            const float* inc = &sin2[ci*196];
            int cig = cc + ci;
            #pragma unroll
            for (int ky = 0; ky < 4; ky++) {
                int iy = 2*oy + ky - 1;
                if ((unsigned)iy >= 14u) continue;
                float rE[16];
                rE[0] = 0.f; rE[15] = 0.f;
                #pragma unroll
                for (int t = 0; t < 14; t++) rE[t+1] = inc[iy*14 + t];
                float4 wv[4];
                #pragma unroll
                for (int u = 0; u < 4; u++)
                    wv[u] = *reinterpret_cast<const float4*>(&w[(size_t)((co+u)*64 + cig)*16 + ky*4]);
                #pragma unroll
                for (int ox = 0; ox < 7; ox++) {
                    int p = 2*ox;
                    float e0 = rE[p], e1 = rE[p+1], e2 = rE[p+2], e3 = rE[p+3];
                    #pragma unroll
                    for (int u = 0; u < 4; u++)
                        acc[u][ox] += e0*wv[u].x + e1*wv[u].y + e2*wv[u].z + e3*wv[u].w;
                }
            }
        }
    }
    #pragma unroll
    for (int u = 0; u < 4; u++) {
        float s = 0.f, q = 0.f;
        #pragma unroll
        for (int ox = 0; ox < 7; ox++) {
            float v = acc[u][ox];
            g_h2[(size_t)(b*128 + co+u)*49 + oy*7 + ox] = v;
            s += v; q += v*v;
        }
        g_ps[(size_t)b*896 + (co+u)*7 + oy] = s;   // layout B: stride=896, P=7
        g_pq[(size_t)b*896 + (co+u)*7 + oy] = q;
    }
}

// ---------------- SGEMM NT, KB=32, 2 CTAs/SM: C[M,N] = act(A)[M,K] * W[N,K]^T (+bias) ----------------
// MODE 1: latent GEMM, A gets bn2-affine + leaky (c=k/49), split-K partial output.
// MODE 0: fc GEMM; A = xlat + radius*gamma fused on load; bias + fused BN stats (layout A, S=16).
template<int MODE>
__global__ void __launch_bounds__(256, 2) sgemm_nt(
    const float* __restrict__ A, const float* __restrict__ W,
    const float* __restrict__ bias, float* __restrict__ out,
    int M, int N, int K, int Ktile,
    const float* __restrict__ ca, const float* __restrict__ cb,
    const float* __restrict__ radius, const float* __restrict__ gamma)
{
    __shared__ float As[32][128];
    __shared__ float Bs[32][128];
    const int tid = threadIdx.x;
    const int bm = blockIdx.y * 128;
    const int bn = blockIdx.x * 128;
    const int lr = tid >> 2;          // 0..63
    const int lc = (tid & 3) << 3;    // 0,8,16,24
    const int tm = (tid >> 4) << 3;
    const int tn = (tid & 15) << 3;
    float acc[8][8];
    #pragma unroll
    for (int i = 0; i < 8; i++)
        #pragma unroll
        for (int j = 0; j < 8; j++) acc[i][j] = 0.f;

    float gm = (MODE == 0) ? gamma[0] : 0.f;

    const int k0beg = blockIdx.z * Ktile;
    for (int k0 = k0beg; k0 < k0beg + Ktile; k0 += 32) {
        #pragma unroll
        for (int h = 0; h < 2; h++) {
            int row = bm + lr + (h << 6);
            const float* ap = A + (size_t)row*K + k0 + lc;
            float4 v0 = *reinterpret_cast<const float4*>(ap);
            float4 v1 = *reinterpret_cast<const float4*>(ap + 4);
            if (MODE == 1) {
                int kb = k0 + lc;
                int c0=(kb  )/49, c1=(kb+1)/49, c2=(kb+2)/49, c3=(kb+3)/49;
                int c4=(kb+4)/49, c5=(kb+5)/49, c6=(kb+6)/49, c7=(kb+7)/49;
                v0.x = leakyf(ca[c0]*v0.x + cb[c0]);
                v0.y = leakyf(ca[c1]*v0.y + cb[c1]);
                v0.z = leakyf(ca[c2]*v0.z + cb[c2]);
                v0.w = leakyf(ca[c3]*v0.w + cb[c3]);
                v1.x = leakyf(ca[c4]*v1.x + cb[c4]);
                v1.y = leakyf(ca[c5]*v1.y + cb[c5]);
                v1.z = leakyf(ca[c6]*v1.z + cb[c6]);
                v1.w = leakyf(ca[c7]*v1.w + cb[c7]);
            } else {
                int wdx = row >> 5;   // class index (row / SHOT)
                const float* rp = radius + (wdx << 9) + k0 + lc;
                float4 r0 = *reinterpret_cast<const float4*>(rp);
                float4 r1 = *reinterpret_cast<const float4*>(rp + 4);
                v0.x += r0.x * gm; v0.y += r0.y * gm; v0.z += r0.z * gm; v0.w += r0.w * gm;
                v1.x += r1.x * gm; v1.y += r1.y * gm; v1.z += r1.z * gm; v1.w += r1.w * gm;
            }
            int wrow = bn + lr + (h << 6);
            const float* wp = W + (size_t)wrow*K + k0 + lc;
            float4 w0 = *reinterpret_cast<const float4*>(wp);
            float4 w1 = *reinterpret_cast<const float4*>(wp + 4);

            int r = lr + (h << 6);
            As[lc+0][r] = v0.x; As[lc+1][r] = v0.y; As[lc+2][r] = v0.z; As[lc+3][r] = v0.w;
            As[lc+4][r] = v1.x; As[lc+5][r] = v1.y; As[lc+6][r] = v1.z; As[lc+7][r] = v1.w;
            Bs[lc+0][r] = w0.x; Bs[lc+1][r] = w0.y; Bs[lc+2][r] = w0.z; Bs[lc+3][r] = w0.w;
            Bs[lc+4][r] = w1.x; Bs[lc+5][r] = w1.y; Bs[lc+6][r] = w1.z; Bs[lc+7][r] = w1.w;
        }
        __syncthreads();
        #pragma unroll
        for (int kk = 0; kk < 32; kk++) {
            float a[8], bb[8];
            #pragma unroll
            for (int i = 0; i < 8; i++) a[i]  = As[kk][tm+i];
            #pragma unroll
            for (int j = 0; j < 8; j++) bb[j] = Bs[kk][tn+j];
            #pragma unroll
            for (int i = 0; i < 8; i++)
                #pragma unroll
                for (int j = 0; j < 8; j++) acc[i][j] += a[i]*bb[j];
        }
        __syncthreads();
    }

    if (MODE == 0) {
        float cs[8], cq[8];
        #pragma unroll
        for (int j = 0; j < 8; j++) { cs[j] = 0.f; cq[j] = 0.f; }
        #pragma unroll
        for (int i = 0; i < 8; i++) {
            float* o = out + (size_t)(bm+tm+i)*N + bn;
            #pragma unroll
            for (int j = 0; j < 8; j++) {
                float v = acc[i][j] + bias[bn+tn+j];
                o[tn+j] = v;
                cs[j] += v; cq[j] += v*v;
            }
        }
        // reduce per-column partials through As/Bs (free after last loop sync)
        int g = tid >> 4;
        #pragma unroll
        for (int j = 0; j < 8; j++) { As[g][tn+j] = cs[j]; Bs[g][tn+j] = cq[j]; }
        __syncthreads();
        if (tid < 128) {
            float s = 0.f, q = 0.f;
            #pragma unroll
            for (int g2 = 0; g2 < 16; g2++) { s += As[g2][tid]; q += Bs[g2][tid]; }
            g_ps[(size_t)(bn+tid)*16 + blockIdx.y] = s;
            g_pq[(size_t)(bn+tid)*16 + blockIdx.y] = q;
        }
    } else {
        float* P = out + (size_t)blockIdx.z * M * N;
        #pragma unroll
        for (int i = 0; i < 8; i++) {
            float* o = P + (size_t)(bm+tm+i)*N + bn;
            #pragma unroll
            for (int j = 0; j < 8; j++) o[tn+j] = acc[i][j];
        }
    }
}

// ---------------- combine split-K partials + bias, fused latent BN stats (layout A, S=256) ----------------
__global__ void __launch_bounds__(512) combine_lat_stats(const float* __restrict__ bias)
{
    int c = threadIdx.x;
    int s = blockIdx.x;
    float bc = bias[c];
    float sum = 0.f, sq = 0.f;
    for (int r = s*8; r < s*8 + 8; r++) {
        size_t idx = (size_t)r*LAT + c;
        float v = g_gpart[idx] + g_gpart[(size_t)BB*LAT + idx]
                + g_gpart[2*(size_t)BB*LAT + idx] + g_gpart[3*(size_t)BB*LAT + idx] + bc;
        g_lat[idx] = v;
        sum += v; sq += v*v;
    }
    g_ps[(size_t)c*256 + s] = sum;
    g_pq[(size_t)c*256 + s] = sq;
}

// ---------------- fused latent activation + prototypes ----------------
__global__ void __launch_bounds__(512) latent_act_proto(float* __restrict__ xlat,
                                                        float* __restrict__ proto)
{
    int w = blockIdx.x;
    int c = threadIdx.x;
    float a = g_aL[c], bo = g_bL[c];
    float s = 0.f;
    #pragma unroll
    for (int j = 0; j < SHOT; j++) {
        size_t idx = (size_t)(w*SHOT + j)*LAT + c;
        float v = sigmoidf(a*g_lat[idx] + bo);
        xlat[idx] = v;
        s += v;
    }
    proto[w*LAT + c] = s * (1.f/SHOT);
}

__global__ void attn_radius_kernel(const float* __restrict__ proto, float* __restrict__ radius)
{
    int i = blockIdx.x;
    int tid = threadIdx.x;   // 64
    __shared__ float spi[LAT];
    __shared__ float att[WAYS];
    for (int l = tid; l < LAT; l += 64) spi[l] = proto[i*LAT + l];
    __syncthreads();
    float dot = 0.f;
    const float* pj = proto + tid*LAT;
    for (int l = 0; l < LAT; l++) dot += spi[l] * pj[l];
    att[tid] = dot;
    __syncthreads();
    float mx = -1e30f;
    for (int j = 0; j < WAYS; j++) mx = fmaxf(mx, att[j]);
    float ex = __expf(att[tid] - mx);
    __syncthreads();
    att[tid] = ex;
    __syncthreads();
    float sum = 0.f;
    for (int j = 0; j < WAYS; j++) sum += att[j];
    float inv = 1.f / sum;
    for (int r = 0; r < 8; r++) {
        int l = tid + (r << 6);
        float accv = 0.f;
        for (int j = 0; j < WAYS; j++) accv += att[j] * proto[j*LAT + l];
        radius[i*LAT + l] = spi[l] - accv * inv;
    }
}

// ---------------- deconv1: [B,128,7,7] -> [B,64,14,14], bnf fused, free stats ----------------
__global__ void __launch_bounds__(224) deconv1_kernel(const float* __restrict__ w,
                                                      const float* __restrict__ bias)
{
    int b = blockIdx.x;
    __shared__ float sin1[128*49];   // 25088 B
    const float* src = g_fc + (size_t)b * FLATD;
    int tid = threadIdx.x;
    for (int i = tid; i < FLATD; i += 224)
        sin1[i] = g_aF[i] * src[i] + g_bF[i];
    __syncthreads();
    int cg = tid / 14, oy = tid % 14;
    int co = 4*cg;
    float acc[4][14];
    #pragma unroll
    for (int u = 0; u < 4; u++) {
        float bb = bias[co+u];
        #pragma unroll
        for (int j = 0; j < 14; j++) acc[u][j] = bb;
    }
    int kyp = oy & 1;
    for (int ci = 0; ci < 128; ci++) {
        const float* inc = &sin1[ci*49];
        #pragma unroll
        for (int kyi = 0; kyi < 2; kyi++) {
            int ky = kyp + 2*kyi;
            int iy = (oy + ky - 2) >> 1;
            if ((unsigned)iy >= 7u) continue;
            float r[7];
            #pragma unroll
            for (int t = 0; t < 7; t++) r[t] = inc[iy*7 + t];
            float wr[4][4];
            #pragma unroll
            for (int u = 0; u < 4; u++) {
                float4 q = *reinterpret_cast<const float4*>(&w[(size_t)(ci*64 + co+u)*16 + (3-ky)*4]);
                wr[u][0] = q.w; wr[u][1] = q.z; wr[u][2] = q.y; wr[u][3] = q.x;
            }
            #pragma unroll
            for (int ox = 0; ox < 14; ox++) {
                int kxp = ox & 1;
                #pragma unroll
                for (int kxi = 0; kxi < 2; kxi++) {
                    int kx = kxp + 2*kxi;
                    int ix = (ox + kx - 2) >> 1;
                    if ((unsigned)ix < 7u) {
                        float rv = r[ix];
                        #pragma unroll
                        for (int u = 0; u < 4; u++)
                            acc[u][ox] += rv * wr[u][kx];
                    }
                }
            }
        }
    }
    #pragma unroll
    for (int u = 0; u < 4; u++) {
        float s = 0.f, q = 0.f;
        #pragma unroll
        for (int ox = 0; ox < 14; ox++) {
            float v = acc[u][ox];
            g_d1[(size_t)(b*64 + co+u)*196 + oy*14 + ox] = v;
            s += v; q += v*v;
        }
        g_ps[(size_t)b*896 + (co+u)*14 + oy] = s;   // layout B: stride=896, P=14
        g_pq[(size_t)b*896 + (co+u)*14 + oy] = q;
    }
}

// ---------------- deconv2: [B,64,14,14] -> [B,1,28,28], bnd1+leaky fused, fused stats ----------------
__global__ void __launch_bounds__(784) deconv2_kernel(const float* __restrict__ w,
                                                      const float* __restrict__ bias)
{
    int b = blockIdx.x;
    __shared__ float sin3[32*196];   // 25088 B
    __shared__ float swt[1024];
    __shared__ float rs[784], rq[784];
    int tid = threadIdx.x;
    for (int i = tid; i < 1024; i += 784) swt[i] = w[i];

    int oy = tid / 28, ox = tid % 28;
    int kyp = oy & 1, kxp = ox & 1;
    int iy0 = (oy + kyp - 2) >> 1;
    int iy1 = (oy + kyp) >> 1;
    int ix0 = (ox + kxp - 2) >> 1;
    int ix1 = (ox + kxp) >> 1;
    bool vy0 = (unsigned)iy0 < 14u, vy1 = (unsigned)iy1 < 14u;
    bool vx0 = (unsigned)ix0 < 14u, vx1 = (unsigned)ix1 < 14u;
    int o00 = (3-kyp)*4 + (3-kxp);
    int o01 = (3-kyp)*4 + (1-kxp);
    int o10 = (1-kyp)*4 + (3-kxp);
    int o11 = (1-kyp)*4 + (1-kxp);
    float acc = bias[0];

    for (int cc = 0; cc < 64; cc += 32) {
        __syncthreads();
        const float* src = g_d1 + ((size_t)b*64 + cc)*196;
        for (int i = tid; i < 32*196; i += 784) {
            int c = cc + i/196;
            sin3[i] = leakyf(g_aD1[c]*src[i] + g_bD1[c]);
        }
        __syncthreads();
        for (int ci = 0; ci < 32; ci++) {
            const float* sc = &sin3[ci*196];
            const float* wb = &swt[(cc+ci)*16];
            if (vy0 && vx0) acc += sc[iy0*14+ix0] * wb[o00];
            if (vy0 && vx1) acc += sc[iy0*14+ix1] * wb[o01];
            if (vy1 && vx0) acc += sc[iy1*14+ix0] * wb[o10];
            if (vy1 && vx1) acc += sc[iy1*14+ix1] * wb[o11];
        }
    }
    g_d2[(size_t)b*784 + tid] = acc;

    // fused single-channel stats: block reduction of 784 values (layout A, c=0, S=2048)
    rs[tid] = acc; rq[tid] = acc*acc;
    __syncthreads();
    if (tid < 272) { rs[tid] += rs[tid+512]; rq[tid] += rq[tid+512]; }
    __syncthreads();
    for (int st = 256; st > 0; st >>= 1) {
        if (tid < st) { rs[tid] += rs[tid+st]; rq[tid] += rq[tid+st]; }
        __syncthreads();
    }
    if (tid == 0) { g_ps[b] = rs[0]; g_pq[b] = rq[0]; }
}

__global__ void recon_out(float* __restrict__ out)
{
    int idx = blockIdx.x * blockDim.x + threadIdx.x;
    out[idx] = sigmoidf(g_aD2[0] * g_d2[idx] + g_bD2[0]);
}

// ---------------- host ----------------
extern "C" void kernel_launch(void* const* d_in, const int* in_sizes, int n_in,
                              void* d_out, int out_size)
{
    if (n_in < 26) return;
    const float* x      = (const float*)d_in[0];
    const float* gamma  = (const float*)d_in[1];
    const float* c1_w   = (const float*)d_in[2];
    const float* c1_b   = (const float*)d_in[3];
    const float* bn1_s  = (const float*)d_in[4];
    const float* bn1_b  = (const float*)d_in[5];
    const float* c2_w   = (const float*)d_in[6];
    const float* c2_b   = (const float*)d_in[7];
    const float* bn2_s  = (const float*)d_in[8];
    const float* bn2_b  = (const float*)d_in[9];
    const float* lat_w  = (const float*)d_in[10];
    const float* lat_b  = (const float*)d_in[11];
    const float* bnl_s  = (const float*)d_in[12];
    const float* bnl_b  = (const float*)d_in[13];
    const float* fc_w   = (const float*)d_in[14];
    const float* fc_b   = (const float*)d_in[15];
    const float* bnf_s  = (const float*)d_in[16];
    const float* bnf_b  = (const float*)d_in[17];
    const float* d1_w   = (const float*)d_in[18];
    const float* d1_b   = (const float*)d_in[19];
    const float* bnd1_s = (const float*)d_in[20];
    const float* bnd1_b = (const float*)d_in[21];
    const float* d2_w   = (const float*)d_in[22];
    const float* d2_b   = (const float*)d_in[23];
    const float* bnd2_s = (const float*)d_in[24];
    const float* bnd2_b = (const float*)d_in[25];

    float* out     = (float*)d_out;
    float* o_recon = out + OFF_RECON;
    float* o_proto = out + OFF_PROTO;
    float* o_rad   = out + OFF_RAD;
    float* o_lat   = out + OFF_LAT;

    void *p_h2, *p_gpart, *p_fc;
    cudaGetSymbolAddress(&p_h2,    g_h2);
    cudaGetSymbolAddress(&p_gpart, g_gpart);
    cudaGetSymbolAddress(&p_fc,    g_fc);

    void *p_a1, *p_b1, *p_a2, *p_b2, *p_aL, *p_bL, *p_aF, *p_bF, *p_aD1, *p_bD1, *p_aD2, *p_bD2;
    cudaGetSymbolAddress(&p_a1,  g_a1);   cudaGetSymbolAddress(&p_b1,  g_b1);
    cudaGetSymbolAddress(&p_a2,  g_a2);   cudaGetSymbolAddress(&p_b2,  g_b2);
    cudaGetSymbolAddress(&p_aL,  g_aL);   cudaGetSymbolAddress(&p_bL,  g_bL);
    cudaGetSymbolAddress(&p_aF,  g_aF);   cudaGetSymbolAddress(&p_bF,  g_bF);
    cudaGetSymbolAddress(&p_aD1, g_aD1);  cudaGetSymbolAddress(&p_bD1, g_bD1);
    cudaGetSymbolAddress(&p_aD2, g_aD2);  cudaGetSymbolAddress(&p_bD2, g_bD2);

    // ---- encoder ----
    conv1_kernel<<<BB, 256>>>(x, c1_w, c1_b);                       // + h1 stats (layout B)
    bn_finalize3<<<64, 512>>>(BB, 4, 256, 1.f/(BB*196.f), bn1_s, bn1_b, (float*)p_a1, (float*)p_b1);

    conv2_kernel<<<BB, 224>>>(c2_w, c2_b);                          // + h2 stats (layout B)
    bn_finalize3<<<128, 512>>>(BB, 7, 896, 1.f/(BB*49.f), bn2_s, bn2_b, (float*)p_a2, (float*)p_b2);

    // latent GEMM (split-K=4, KB=32), bn2+leaky fused into A load
    sgemm_nt<1><<<dim3(LAT/128, BB/128, 4), 256>>>(
        (const float*)p_h2, lat_w, nullptr, (float*)p_gpart,
        BB, LAT, FLATD, FLATD/4, (const float*)p_a2, (const float*)p_b2,
        nullptr, nullptr);
    combine_lat_stats<<<256, 512>>>(lat_b);                         // + lat stats (layout A, S=256)
    bn_finalize2<<<LAT, 128>>>(256, 1.f/(float)BB, bnl_s, bnl_b, (float*)p_aL, (float*)p_bL);

    // ---- prototypes / radius (latent activation fused into proto pass) ----
    latent_act_proto<<<WAYS, LAT>>>(o_lat, o_proto);
    attn_radius_kernel<<<WAYS, 64>>>(o_proto, o_rad);

    // ---- decoder ----
    // fc GEMM (KB=32); recon-latent shift (xlat + radius*gamma) fused into A load
    sgemm_nt<0><<<dim3(FLATD/128, BB/128, 1), 256>>>(               // + fc stats (layout A, S=16)
        o_lat, fc_w, fc_b, (float*)p_fc,
        BB, FLATD, LAT, LAT, nullptr, nullptr,
        o_rad, gamma);
    bn_finalize2<<<FLATD, 128>>>(16, 1.f/(float)BB, bnf_s, bnf_b, (float*)p_aF, (float*)p_bF);

    deconv1_kernel<<<BB, 224>>>(d1_w, d1_b);                        // + d1 stats (layout B)
    bn_finalize3<<<64, 512>>>(BB, 14, 896, 1.f/(BB*196.f), bnd1_s, bnd1_b, (float*)p_aD1, (float*)p_bD1);

    deconv2_kernel<<<BB, 784>>>(d2_w, d2_b);                        // + d2 stats (layout A, S=2048)
    bn_finalize2<<<1, 128>>>(2048, 1.f/(BB*784.f), bnd2_s, bnd2_b, (float*)p_aD2, (float*)p_bD2);

    recon_out<<<BB*784/256, 256>>>(o_recon);
}